// round 5
// baseline (speedup 1.0000x reference)
#include <cuda_runtime.h>
#include <math.h>

#define NN   100000
#define EE   300000
#define DINF 128
#define HH   512
#define GG   4096
#define OUTC 256
#define SLOPE 0.01f
#define EPS   1e-5f

// -------- scratch (device globals: allocation-free, 256B aligned) --------
__device__ __align__(256) float    g_deg[NN];
__device__ __align__(256) float    g_dinv[NN];
__device__ __align__(256) float    g_selfc[NN];
__device__ __align__(256) float    g_norm[EE];
__device__ __align__(256) float    g_buf1[(size_t)NN * HH];
__device__ __align__(256) float    g_buf2[(size_t)NN * HH];
__device__ __align__(256) float    g_buf3[(size_t)NN * HH];
__device__ __align__(256) unsigned g_keys[(size_t)GG * HH];
__device__ __align__(256) float    g_pooled[(size_t)GG * HH];
__device__ __align__(256) float    g_stats[4 * HH];
__device__ __align__(256) float    g_bna[HH];
__device__ __align__(256) float    g_bnc[HH];

// -------- init --------
__global__ void init_kernel() {
    int i = blockIdx.x * blockDim.x + threadIdx.x;
    if (i < NN) g_deg[i] = 2.0f;
    if (i < GG * HH) g_keys[i] = 0u;
    if (i < 4 * HH) g_stats[i] = 0.0f;
}

__global__ void count_deg_kernel(const int* __restrict__ ecol) {
    int e = blockIdx.x * blockDim.x + threadIdx.x;
    if (e < EE) atomicAdd(&g_deg[ecol[e]], 1.0f);
}

__global__ void dinv_kernel() {
    int i = blockIdx.x * blockDim.x + threadIdx.x;
    if (i < NN) {
        float d = g_deg[i];
        float di = rsqrtf(d);
        g_dinv[i] = di;
        g_selfc[i] = 2.0f * di * di;
    }
}

__global__ void edge_norm_kernel(const int* __restrict__ erow,
                                 const int* __restrict__ ecol) {
    int e = blockIdx.x * blockDim.x + threadIdx.x;
    if (e < EE) g_norm[e] = g_dinv[erow[e]] * g_dinv[ecol[e]];
}

// -------- register-tiled SGEMM (R3-proven): C=A@B(+bias); opt out2=bias2+selfc[r]*C --------
#define BM 128
#define BN 128
#define BK 8
#define TM 8
#define TN 8

__global__ __launch_bounds__(256)
void sgemm_kernel(const float* __restrict__ A, const float* __restrict__ B,
                  const float* __restrict__ bias, float* __restrict__ C,
                  const float* __restrict__ selfc, const float* __restrict__ bias2,
                  float* __restrict__ out2,
                  int M, int N, int K) {
    __shared__ float As[BK][BM];
    __shared__ float Bs[BK][BN];
    int tid = threadIdx.x;
    int bm = blockIdx.y * BM;
    int bn = blockIdx.x * BN;
    int tcol = tid % 16;
    int trow = tid / 16;

    float acc[TM][TN];
#pragma unroll
    for (int i = 0; i < TM; i++)
#pragma unroll
        for (int j = 0; j < TN; j++) acc[i][j] = 0.0f;

    int aRow = tid >> 1;
    int aCol = (tid & 1) * 4;
    int bRow = tid >> 5;
    int bCol = (tid & 31) * 4;

    const float* Ablk = A + (long long)bm * K;

    for (int k0 = 0; k0 < K; k0 += BK) {
        float4 av;
        if (bm + aRow < M)
            av = *reinterpret_cast<const float4*>(Ablk + (long long)aRow * K + k0 + aCol);
        else
            av = make_float4(0.f, 0.f, 0.f, 0.f);
        As[aCol + 0][aRow] = av.x;
        As[aCol + 1][aRow] = av.y;
        As[aCol + 2][aRow] = av.z;
        As[aCol + 3][aRow] = av.w;

        float4 bv = *reinterpret_cast<const float4*>(B + (long long)(k0 + bRow) * N + bn + bCol);
        *reinterpret_cast<float4*>(&Bs[bRow][bCol]) = bv;
        __syncthreads();

#pragma unroll
        for (int k = 0; k < BK; k++) {
            float ra[TM], rb[TN];
#pragma unroll
            for (int i = 0; i < TM; i++) ra[i] = As[k][trow * TM + i];
#pragma unroll
            for (int j = 0; j < TN; j++) rb[j] = Bs[k][tcol * TN + j];
#pragma unroll
            for (int i = 0; i < TM; i++)
#pragma unroll
                for (int j = 0; j < TN; j++) acc[i][j] += ra[i] * rb[j];
        }
        __syncthreads();
    }

    for (int i = 0; i < TM; i++) {
        int r = bm + trow * TM + i;
        if (r >= M) break;
        float sc = out2 ? selfc[r] : 0.0f;
#pragma unroll
        for (int j = 0; j < TN; j += 4) {
            int cidx = bn + tcol * TN + j;
            float4 v = make_float4(acc[i][j], acc[i][j + 1], acc[i][j + 2], acc[i][j + 3]);
            if (bias) {
                v.x += bias[cidx]; v.y += bias[cidx + 1];
                v.z += bias[cidx + 2]; v.w += bias[cidx + 3];
            }
            *reinterpret_cast<float4*>(C + (long long)r * N + cidx) = v;
            if (out2) {
                float4 o;
                o.x = bias2[cidx + 0] + v.x * sc;
                o.y = bias2[cidx + 1] + v.y * sc;
                o.z = bias2[cidx + 2] + v.z * sc;
                o.w = bias2[cidx + 3] + v.w * sc;
                *reinterpret_cast<float4*>(out2 + (long long)r * N + cidx) = o;
            }
        }
    }
}

// -------- edge scatter: out[col] += norm * h[row] --------
__global__ void agg_edges_kernel(const float* __restrict__ h,
                                 const int* __restrict__ erow,
                                 const int* __restrict__ ecol,
                                 float* __restrict__ out) {
    long long gid = (long long)blockIdx.x * blockDim.x + threadIdx.x;
    int e = (int)(gid >> 7);
    int c4 = (int)(gid & 127);
    if (e >= EE) return;
    int r = erow[e];
    int c = ecol[e];
    float nm = g_norm[e];
    float4 v = *reinterpret_cast<const float4*>(h + (long long)r * HH + c4 * 4);
    float* dst = out + (long long)c * HH + c4 * 4;
    asm volatile("red.global.add.v4.f32 [%0], {%1, %2, %3, %4};"
                 :: "l"(dst), "f"(v.x * nm), "f"(v.y * nm), "f"(v.z * nm), "f"(v.w * nm)
                 : "memory");
}

// -------- batchnorm --------
__global__ void bn_stats_kernel(const float* __restrict__ X, float* __restrict__ sum,
                                float* __restrict__ sumsq) {
    int f = threadIdx.x;
    float s = 0.f, s2 = 0.f;
    for (int r = blockIdx.x; r < NN; r += gridDim.x) {
        float v = X[(long long)r * HH + f];
        s += v;
        s2 += v * v;
    }
    atomicAdd(&sum[f], s);
    atomicAdd(&sumsq[f], s2);
}

__global__ void bn_coef_kernel(const float* __restrict__ sum, const float* __restrict__ sumsq,
                               const float* __restrict__ g, const float* __restrict__ beta) {
    int f = threadIdx.x;
    float invN = 1.0f / (float)NN;
    float mu = sum[f] * invN;
    float var = fmaxf(sumsq[f] * invN - mu * mu, 0.0f);
    float s = g[f] * rsqrtf(var + EPS);
    g_bna[f] = s;
    g_bnc[f] = beta[f] - s * mu;
}

__global__ void bn_apply_kernel(const float* __restrict__ X, float* __restrict__ Y) {
    long long i4 = (long long)blockIdx.x * blockDim.x + threadIdx.x;
    long long base = i4 * 4;
    if (base >= (long long)NN * HH) return;
    int f = (int)(base & 511);
    float4 v = *reinterpret_cast<const float4*>(X + base);
    float4 a = *reinterpret_cast<const float4*>(g_bna + f);
    float4 c = *reinterpret_cast<const float4*>(g_bnc + f);
    float4 o;
    o.x = fmaf(a.x, v.x, c.x); o.y = fmaf(a.y, v.y, c.y);
    o.z = fmaf(a.z, v.z, c.z); o.w = fmaf(a.w, v.w, c.w);
    o.x = o.x > 0.f ? o.x : SLOPE * o.x;
    o.y = o.y > 0.f ? o.y : SLOPE * o.y;
    o.z = o.z > 0.f ? o.z : SLOPE * o.z;
    o.w = o.w > 0.f ? o.w : SLOPE * o.w;
    *reinterpret_cast<float4*>(Y + base) = o;
}

// -------- fused BN-apply + LeakyReLU + segment-max pool (layer 2) --------
__global__ void bn_pool_kernel(const float* __restrict__ X, const int* __restrict__ batch) {
    long long i4 = (long long)blockIdx.x * blockDim.x + threadIdx.x;
    long long base = i4 * 4;
    if (base >= (long long)NN * HH) return;
    int node = (int)(base >> 9);
    int f = (int)(base & 511);
    int grp = batch[node];
    float4 v = *reinterpret_cast<const float4*>(X + base);
    float4 a = *reinterpret_cast<const float4*>(g_bna + f);
    float4 c = *reinterpret_cast<const float4*>(g_bnc + f);
    float o[4];
    o[0] = fmaf(a.x, v.x, c.x); o[1] = fmaf(a.y, v.y, c.y);
    o[2] = fmaf(a.z, v.z, c.z); o[3] = fmaf(a.w, v.w, c.w);
    unsigned* dst = &g_keys[(long long)grp * HH + f];
#pragma unroll
    for (int j = 0; j < 4; j++) {
        float ov = o[j] > 0.f ? o[j] : SLOPE * o[j];
        unsigned u = __float_as_uint(ov);
        u = (u & 0x80000000u) ? ~u : (u | 0x80000000u);
        atomicMax(&dst[j], u);
    }
}

__global__ void pool_decode_kernel() {
    long long i = (long long)blockIdx.x * blockDim.x + threadIdx.x;
    if (i >= (long long)GG * HH) return;
    unsigned k = g_keys[i];
    float v;
    if (k == 0u) {
        v = 0.0f;
    } else {
        unsigned u = (k & 0x80000000u) ? (k & 0x7fffffffu) : ~k;
        v = __uint_as_float(u);
    }
    g_pooled[i] = v;
}

// -------- host launch --------
extern "C" void kernel_launch(void* const* d_in, const int* in_sizes, int n_in,
                              void* d_out, int out_size) {
    const float* x      = (const float*)d_in[0];
    const int*   ei     = (const int*)d_in[1];
    const int*   bt     = (const int*)d_in[2];
    const float* W1     = (const float*)d_in[3];
    const float* b1     = (const float*)d_in[4];
    const float* g1     = (const float*)d_in[5];
    const float* beta1  = (const float*)d_in[6];
    const float* W2     = (const float*)d_in[7];
    const float* b2     = (const float*)d_in[8];
    const float* g2     = (const float*)d_in[9];
    const float* beta2  = (const float*)d_in[10];
    const float* Wf     = (const float*)d_in[11];
    const float* bf     = (const float*)d_in[12];
    float* out = (float*)d_out;

    const int* erow = ei;
    const int* ecol = ei + EE;

    float *buf1, *buf2, *buf3, *pooled, *stats, *selfc;
    cudaGetSymbolAddress((void**)&buf1, g_buf1);
    cudaGetSymbolAddress((void**)&buf2, g_buf2);
    cudaGetSymbolAddress((void**)&buf3, g_buf3);
    cudaGetSymbolAddress((void**)&pooled, g_pooled);
    cudaGetSymbolAddress((void**)&stats, g_stats);
    cudaGetSymbolAddress((void**)&selfc, g_selfc);

    const int T = 256;
    init_kernel<<<(GG * HH + T - 1) / T, T>>>();
    count_deg_kernel<<<(EE + T - 1) / T, T>>>(ecol);
    dinv_kernel<<<(NN + T - 1) / T, T>>>();
    edge_norm_kernel<<<(EE + T - 1) / T, T>>>(erow, ecol);

    long long elems = (long long)NN * HH;
    int blk_elem4 = (int)((elems / 4 + T - 1) / T);
    int blk_edges = (int)(((long long)EE * 128 + T - 1) / T);

    // ---- layer 1: GEMM (h1 -> buf1, fused pre-agg b1+selfc*h1 -> buf2) ----
    {
        dim3 grid(HH / BN, (NN + BM - 1) / BM);
        sgemm_kernel<<<grid, 256>>>(x, W1, nullptr, buf1, selfc, b1, buf2, NN, HH, DINF);
    }
    agg_edges_kernel<<<blk_edges, T>>>(buf1, erow, ecol, buf2);
    bn_stats_kernel<<<1024, HH>>>(buf2, stats + 0, stats + HH);
    bn_coef_kernel<<<1, HH>>>(stats + 0, stats + HH, g1, beta1);
    bn_apply_kernel<<<blk_elem4, T>>>(buf2, buf1);

    // ---- layer 2: GEMM (h2 -> buf2, fused pre-agg b2+selfc*h2 -> buf3) ----
    {
        dim3 grid(HH / BN, (NN + BM - 1) / BM);
        sgemm_kernel<<<grid, 256>>>(buf1, W2, nullptr, buf2, selfc, b2, buf3, NN, HH, HH);
    }
    agg_edges_kernel<<<blk_edges, T>>>(buf2, erow, ecol, buf3);
    bn_stats_kernel<<<1024, HH>>>(buf3, stats + 2 * HH, stats + 3 * HH);
    bn_coef_kernel<<<1, HH>>>(stats + 2 * HH, stats + 3 * HH, g2, beta2);
    bn_pool_kernel<<<blk_elem4, T>>>(buf3, bt);

    // ---- pool decode + final linear ----
    pool_decode_kernel<<<(GG * HH + T - 1) / T, T>>>();
    {
        dim3 grid(OUTC / BN, (GG + BM - 1) / BM);
        sgemm_kernel<<<grid, 256>>>(pooled, Wf, bf, out, nullptr, nullptr, nullptr, GG, OUTC, HH);
    }
}

// round 6
// speedup vs baseline: 1.4858x; 1.4858x over previous
#include <cuda_runtime.h>
#include <math.h>

#define NN   100000
#define EE   300000
#define DINF 128
#define HH   512
#define GG   4096
#define OUTC 256
#define SLOPE 0.01f
#define EPS   1e-5f

// -------- scratch (device globals: allocation-free, 256B aligned) --------
__device__ __align__(256) float    g_deg[NN];
__device__ __align__(256) float    g_dinv[NN];
__device__ __align__(256) float    g_selfc[NN];
__device__ __align__(256) float    g_norm[EE];
__device__ __align__(256) float    g_buf1[(size_t)NN * HH];
__device__ __align__(256) float    g_buf2[(size_t)NN * HH];
__device__ __align__(256) float    g_buf3[(size_t)NN * HH];
__device__ __align__(256) unsigned g_keys[(size_t)GG * HH];
__device__ __align__(256) float    g_pooled[(size_t)GG * HH];
__device__ __align__(256) float    g_stats[4 * HH];
__device__ __align__(256) float    g_bna[HH];
__device__ __align__(256) float    g_bnc[HH];

// -------- init --------
__global__ void init_kernel() {
    int i = blockIdx.x * blockDim.x + threadIdx.x;
    if (i < NN) g_deg[i] = 2.0f;
    if (i < GG * HH) g_keys[i] = 0u;
    if (i < 4 * HH) g_stats[i] = 0.0f;
}

__global__ void count_deg_kernel(const int* __restrict__ ecol) {
    int e = blockIdx.x * blockDim.x + threadIdx.x;
    if (e < EE) atomicAdd(&g_deg[ecol[e]], 1.0f);
}

__global__ void dinv_kernel() {
    int i = blockIdx.x * blockDim.x + threadIdx.x;
    if (i < NN) {
        float d = g_deg[i];
        float di = rsqrtf(d);
        g_dinv[i] = di;
        g_selfc[i] = 2.0f * di * di;
    }
}

__global__ void edge_norm_kernel(const int* __restrict__ erow,
                                 const int* __restrict__ ecol) {
    int e = blockIdx.x * blockDim.x + threadIdx.x;
    if (e < EE) g_norm[e] = g_dinv[erow[e]] * g_dinv[ecol[e]];
}

// -------- TF32 3-split tensor-core GEMM --------
// C = A@B (+bias); optional out2 = bias2 + selfc[r]*C
#define BM 128
#define BN 128
#define BKT 16
#define SST 136   // shared stride (136 % 32 == 8 -> conflict-free B frag loads)

__device__ __forceinline__ void tf32_split(float x, unsigned &hi, unsigned &lo) {
    unsigned h;
    asm("cvt.rna.tf32.f32 %0, %1;" : "=r"(h) : "f"(x));
    float r = x - __uint_as_float(h);
    unsigned l;
    asm("cvt.rna.tf32.f32 %0, %1;" : "=r"(l) : "f"(r));
    hi = h; lo = l;
}

__device__ __forceinline__ void mma_tf32(float c[4], const unsigned a[4],
                                         unsigned b0, unsigned b1) {
    asm("mma.sync.aligned.m16n8k8.row.col.f32.tf32.tf32.f32 "
        "{%0,%1,%2,%3},{%4,%5,%6,%7},{%8,%9},{%0,%1,%2,%3};"
        : "+f"(c[0]), "+f"(c[1]), "+f"(c[2]), "+f"(c[3])
        : "r"(a[0]), "r"(a[1]), "r"(a[2]), "r"(a[3]), "r"(b0), "r"(b1));
}

__global__ __launch_bounds__(256)
void gemm_tf32(const float* __restrict__ A, const float* __restrict__ B,
               const float* __restrict__ bias, float* __restrict__ C,
               const float* __restrict__ selfc, const float* __restrict__ bias2,
               float* __restrict__ out2,
               int M, int N, int K) {
    __shared__ float Ah[BKT][SST], Al[BKT][SST];
    __shared__ float Bh[BKT][SST], Bl[BKT][SST];

    int tid  = threadIdx.x;
    int lane = tid & 31;
    int warp = tid >> 5;
    int warpM = warp & 3;    // 4 warps down M: 32 rows each
    int warpN = warp >> 2;   // 2 warps across N: 64 cols each
    int bm = blockIdx.y * BM;
    int bn = blockIdx.x * BN;

    float acc[2][8][4];      // [mtile16][ntile8][reg]
#pragma unroll
    for (int i = 0; i < 2; i++)
#pragma unroll
        for (int j = 0; j < 8; j++)
#pragma unroll
            for (int r = 0; r < 4; r++) acc[i][j][r] = 0.0f;

    int arow = tid >> 1;            // 0..127
    int ac0  = (tid & 1) * 8;       // 0 or 8
    int brow = tid >> 4;            // 0..15
    int bc0  = (tid & 15) * 8;      // 0..120

    for (int k0 = 0; k0 < K; k0 += BKT) {
        // ---- load + split A tile (128 x 16), store transposed [k][m] ----
        float av[8];
        if (bm + arow < M) {
            const float* ap = A + (long long)(bm + arow) * K + k0 + ac0;
            float4 a0 = *reinterpret_cast<const float4*>(ap);
            float4 a1 = *reinterpret_cast<const float4*>(ap + 4);
            av[0] = a0.x; av[1] = a0.y; av[2] = a0.z; av[3] = a0.w;
            av[4] = a1.x; av[5] = a1.y; av[6] = a1.z; av[7] = a1.w;
        } else {
#pragma unroll
            for (int j = 0; j < 8; j++) av[j] = 0.0f;
        }
#pragma unroll
        for (int j = 0; j < 8; j++) {
            unsigned h, l;
            tf32_split(av[j], h, l);
            Ah[ac0 + j][arow] = __uint_as_float(h);
            Al[ac0 + j][arow] = __uint_as_float(l);
        }
        // ---- load + split B tile (16 x 128), store [k][n] ----
        {
            const float* bp = B + (long long)(k0 + brow) * N + bn + bc0;
            float4 b0v = *reinterpret_cast<const float4*>(bp);
            float4 b1v = *reinterpret_cast<const float4*>(bp + 4);
            float bv[8] = {b0v.x, b0v.y, b0v.z, b0v.w, b1v.x, b1v.y, b1v.z, b1v.w};
#pragma unroll
            for (int j = 0; j < 8; j++) {
                unsigned h, l;
                tf32_split(bv[j], h, l);
                Bh[brow][bc0 + j] = __uint_as_float(h);
                Bl[brow][bc0 + j] = __uint_as_float(l);
            }
        }
        __syncthreads();

#pragma unroll
        for (int kk = 0; kk < BKT; kk += 8) {
            // A fragments for 2 m-tiles (hi & lo)
            unsigned ahi[2][4], alo[2][4];
            int kc = kk + (lane & 3);
            int r0 = warpM * 32 + (lane >> 2);
#pragma unroll
            for (int mt = 0; mt < 2; mt++) {
                int r = r0 + mt * 16;
                ahi[mt][0] = __float_as_uint(Ah[kc][r]);
                ahi[mt][1] = __float_as_uint(Ah[kc][r + 8]);
                ahi[mt][2] = __float_as_uint(Ah[kc + 4][r]);
                ahi[mt][3] = __float_as_uint(Ah[kc + 4][r + 8]);
                alo[mt][0] = __float_as_uint(Al[kc][r]);
                alo[mt][1] = __float_as_uint(Al[kc][r + 8]);
                alo[mt][2] = __float_as_uint(Al[kc + 4][r]);
                alo[mt][3] = __float_as_uint(Al[kc + 4][r + 8]);
            }
            int kr = kk + (lane & 3);
            int cb = warpN * 64 + (lane >> 2);
#pragma unroll
            for (int nt = 0; nt < 8; nt++) {
                int c = cb + nt * 8;
                unsigned bh0 = __float_as_uint(Bh[kr][c]);
                unsigned bh1 = __float_as_uint(Bh[kr + 4][c]);
                unsigned bl0 = __float_as_uint(Bl[kr][c]);
                unsigned bl1 = __float_as_uint(Bl[kr + 4][c]);
#pragma unroll
                for (int mt = 0; mt < 2; mt++) {
                    mma_tf32(acc[mt][nt], ahi[mt], bh0, bh1);
                    mma_tf32(acc[mt][nt], ahi[mt], bl0, bl1);
                    mma_tf32(acc[mt][nt], alo[mt], bh0, bh1);
                }
            }
        }
        __syncthreads();
    }

    // ---- epilogue ----
#pragma unroll
    for (int mt = 0; mt < 2; mt++) {
#pragma unroll
        for (int half = 0; half < 2; half++) {
            int row = bm + warpM * 32 + mt * 16 + (lane >> 2) + half * 8;
            if (row >= M) continue;
            float sc = out2 ? selfc[row] : 0.0f;
#pragma unroll
            for (int nt = 0; nt < 8; nt++) {
                int col = bn + warpN * 64 + nt * 8 + (lane & 3) * 2;
                float v0 = acc[mt][nt][half * 2 + 0];
                float v1 = acc[mt][nt][half * 2 + 1];
                if (bias) { v0 += bias[col]; v1 += bias[col + 1]; }
                float2 s = make_float2(v0, v1);
                *reinterpret_cast<float2*>(C + (long long)row * N + col) = s;
                if (out2) {
                    float2 o = make_float2(bias2[col] + v0 * sc,
                                           bias2[col + 1] + v1 * sc);
                    *reinterpret_cast<float2*>(out2 + (long long)row * N + col) = o;
                }
            }
        }
    }
}

// -------- edge scatter: out[col] += norm * h[row] --------
__global__ void agg_edges_kernel(const float* __restrict__ h,
                                 const int* __restrict__ erow,
                                 const int* __restrict__ ecol,
                                 float* __restrict__ out) {
    long long gid = (long long)blockIdx.x * blockDim.x + threadIdx.x;
    int e = (int)(gid >> 7);
    int c4 = (int)(gid & 127);
    if (e >= EE) return;
    int r = erow[e];
    int c = ecol[e];
    float nm = g_norm[e];
    float4 v = *reinterpret_cast<const float4*>(h + (long long)r * HH + c4 * 4);
    float* dst = out + (long long)c * HH + c4 * 4;
    asm volatile("red.global.add.v4.f32 [%0], {%1, %2, %3, %4};"
                 :: "l"(dst), "f"(v.x * nm), "f"(v.y * nm), "f"(v.z * nm), "f"(v.w * nm)
                 : "memory");
}

// -------- batchnorm --------
__global__ void bn_stats_kernel(const float* __restrict__ X, float* __restrict__ sum,
                                float* __restrict__ sumsq) {
    int f = threadIdx.x;
    float s = 0.f, s2 = 0.f;
    for (int r = blockIdx.x; r < NN; r += gridDim.x) {
        float v = X[(long long)r * HH + f];
        s += v;
        s2 += v * v;
    }
    atomicAdd(&sum[f], s);
    atomicAdd(&sumsq[f], s2);
}

__global__ void bn_coef_kernel(const float* __restrict__ sum, const float* __restrict__ sumsq,
                               const float* __restrict__ g, const float* __restrict__ beta) {
    int f = threadIdx.x;
    float invN = 1.0f / (float)NN;
    float mu = sum[f] * invN;
    float var = fmaxf(sumsq[f] * invN - mu * mu, 0.0f);
    float s = g[f] * rsqrtf(var + EPS);
    g_bna[f] = s;
    g_bnc[f] = beta[f] - s * mu;
}

__global__ void bn_apply_kernel(const float* __restrict__ X, float* __restrict__ Y) {
    long long i4 = (long long)blockIdx.x * blockDim.x + threadIdx.x;
    long long base = i4 * 4;
    if (base >= (long long)NN * HH) return;
    int f = (int)(base & 511);
    float4 v = *reinterpret_cast<const float4*>(X + base);
    float4 a = *reinterpret_cast<const float4*>(g_bna + f);
    float4 c = *reinterpret_cast<const float4*>(g_bnc + f);
    float4 o;
    o.x = fmaf(a.x, v.x, c.x); o.y = fmaf(a.y, v.y, c.y);
    o.z = fmaf(a.z, v.z, c.z); o.w = fmaf(a.w, v.w, c.w);
    o.x = o.x > 0.f ? o.x : SLOPE * o.x;
    o.y = o.y > 0.f ? o.y : SLOPE * o.y;
    o.z = o.z > 0.f ? o.z : SLOPE * o.z;
    o.w = o.w > 0.f ? o.w : SLOPE * o.w;
    *reinterpret_cast<float4*>(Y + base) = o;
}

// -------- fused BN-apply + LeakyReLU + segment-max pool (layer 2) --------
__global__ void bn_pool_kernel(const float* __restrict__ X, const int* __restrict__ batch) {
    long long i4 = (long long)blockIdx.x * blockDim.x + threadIdx.x;
    long long base = i4 * 4;
    if (base >= (long long)NN * HH) return;
    int node = (int)(base >> 9);
    int f = (int)(base & 511);
    int grp = batch[node];
    float4 v = *reinterpret_cast<const float4*>(X + base);
    float4 a = *reinterpret_cast<const float4*>(g_bna + f);
    float4 c = *reinterpret_cast<const float4*>(g_bnc + f);
    float o[4];
    o[0] = fmaf(a.x, v.x, c.x); o[1] = fmaf(a.y, v.y, c.y);
    o[2] = fmaf(a.z, v.z, c.z); o[3] = fmaf(a.w, v.w, c.w);
    unsigned* dst = &g_keys[(long long)grp * HH + f];
#pragma unroll
    for (int j = 0; j < 4; j++) {
        float ov = o[j] > 0.f ? o[j] : SLOPE * o[j];
        unsigned u = __float_as_uint(ov);
        u = (u & 0x80000000u) ? ~u : (u | 0x80000000u);
        atomicMax(&dst[j], u);
    }
}

__global__ void pool_decode_kernel() {
    long long i = (long long)blockIdx.x * blockDim.x + threadIdx.x;
    if (i >= (long long)GG * HH) return;
    unsigned k = g_keys[i];
    float v;
    if (k == 0u) {
        v = 0.0f;
    } else {
        unsigned u = (k & 0x80000000u) ? (k & 0x7fffffffu) : ~k;
        v = __uint_as_float(u);
    }
    g_pooled[i] = v;
}

// -------- host launch --------
extern "C" void kernel_launch(void* const* d_in, const int* in_sizes, int n_in,
                              void* d_out, int out_size) {
    const float* x      = (const float*)d_in[0];
    const int*   ei     = (const int*)d_in[1];
    const int*   bt     = (const int*)d_in[2];
    const float* W1     = (const float*)d_in[3];
    const float* b1     = (const float*)d_in[4];
    const float* g1     = (const float*)d_in[5];
    const float* beta1  = (const float*)d_in[6];
    const float* W2     = (const float*)d_in[7];
    const float* b2     = (const float*)d_in[8];
    const float* g2     = (const float*)d_in[9];
    const float* beta2  = (const float*)d_in[10];
    const float* Wf     = (const float*)d_in[11];
    const float* bf     = (const float*)d_in[12];
    float* out = (float*)d_out;

    const int* erow = ei;
    const int* ecol = ei + EE;

    float *buf1, *buf2, *buf3, *pooled, *stats, *selfc;
    cudaGetSymbolAddress((void**)&buf1, g_buf1);
    cudaGetSymbolAddress((void**)&buf2, g_buf2);
    cudaGetSymbolAddress((void**)&buf3, g_buf3);
    cudaGetSymbolAddress((void**)&pooled, g_pooled);
    cudaGetSymbolAddress((void**)&stats, g_stats);
    cudaGetSymbolAddress((void**)&selfc, g_selfc);

    const int T = 256;
    init_kernel<<<(GG * HH + T - 1) / T, T>>>();
    count_deg_kernel<<<(EE + T - 1) / T, T>>>(ecol);
    dinv_kernel<<<(NN + T - 1) / T, T>>>();
    edge_norm_kernel<<<(EE + T - 1) / T, T>>>(erow, ecol);

    long long elems = (long long)NN * HH;
    int blk_elem4 = (int)((elems / 4 + T - 1) / T);
    int blk_edges = (int)(((long long)EE * 128 + T - 1) / T);

    // ---- layer 1: GEMM (h1 -> buf1, fused pre-agg b1+selfc*h1 -> buf2) ----
    {
        dim3 grid(HH / BN, (NN + BM - 1) / BM);
        gemm_tf32<<<grid, 256>>>(x, W1, nullptr, buf1, selfc, b1, buf2, NN, HH, DINF);
    }
    agg_edges_kernel<<<blk_edges, T>>>(buf1, erow, ecol, buf2);
    bn_stats_kernel<<<1024, HH>>>(buf2, stats + 0, stats + HH);
    bn_coef_kernel<<<1, HH>>>(stats + 0, stats + HH, g1, beta1);
    bn_apply_kernel<<<blk_elem4, T>>>(buf2, buf1);

    // ---- layer 2: GEMM (h2 -> buf2, fused pre-agg b2+selfc*h2 -> buf3) ----
    {
        dim3 grid(HH / BN, (NN + BM - 1) / BM);
        gemm_tf32<<<grid, 256>>>(buf1, W2, nullptr, buf2, selfc, b2, buf3, NN, HH, HH);
    }
    agg_edges_kernel<<<blk_edges, T>>>(buf2, erow, ecol, buf3);
    bn_stats_kernel<<<1024, HH>>>(buf3, stats + 2 * HH, stats + 3 * HH);
    bn_coef_kernel<<<1, HH>>>(stats + 2 * HH, stats + 3 * HH, g2, beta2);
    bn_pool_kernel<<<blk_elem4, T>>>(buf3, bt);

    // ---- pool decode + final linear ----
    pool_decode_kernel<<<(GG * HH + T - 1) / T, T>>>();
    {
        dim3 grid(OUTC / BN, (GG + BM - 1) / BM);
        gemm_tf32<<<grid, 256>>>(pooled, Wf, bf, out, nullptr, nullptr, nullptr, GG, OUTC, HH);
    }
}

// round 7
// speedup vs baseline: 1.5447x; 1.0396x over previous
#include <cuda_runtime.h>
#include <math.h>

#define NN   100000
#define EE   300000
#define DINF 128
#define HH   512
#define GG   4096
#define OUTC 256
#define SLOPE 0.01f
#define EPS   1e-5f

// -------- scratch (device globals: allocation-free, 256B aligned) --------
__device__ __align__(256) float    g_deg[NN];
__device__ __align__(256) float    g_dinv[NN];
__device__ __align__(256) float    g_selfc[NN];
__device__ __align__(256) float    g_norm[EE];
__device__ __align__(256) float    g_buf1[(size_t)NN * HH];
__device__ __align__(256) float    g_buf2[(size_t)NN * HH];
__device__ __align__(256) float    g_buf3[(size_t)NN * HH];
__device__ __align__(256) unsigned g_keys[(size_t)GG * HH];
__device__ __align__(256) float    g_pooled[(size_t)GG * HH];
__device__ __align__(256) float    g_stats[4 * HH];
__device__ __align__(256) float    g_bna[HH];
__device__ __align__(256) float    g_bnc[HH];

// -------- init --------
__global__ void init_kernel() {
    int i = blockIdx.x * blockDim.x + threadIdx.x;
    if (i < NN) g_deg[i] = 2.0f;
    if (i < GG * HH) g_keys[i] = 0u;
    if (i < 4 * HH) g_stats[i] = 0.0f;
}

__global__ void count_deg_kernel(const int* __restrict__ ecol) {
    int e = blockIdx.x * blockDim.x + threadIdx.x;
    if (e < EE) atomicAdd(&g_deg[ecol[e]], 1.0f);
}

__global__ void dinv_kernel() {
    int i = blockIdx.x * blockDim.x + threadIdx.x;
    if (i < NN) {
        float d = g_deg[i];
        float di = rsqrtf(d);
        g_dinv[i] = di;
        g_selfc[i] = 2.0f * di * di;
    }
}

__global__ void edge_norm_kernel(const int* __restrict__ erow,
                                 const int* __restrict__ ecol) {
    int e = blockIdx.x * blockDim.x + threadIdx.x;
    if (e < EE) g_norm[e] = g_dinv[erow[e]] * g_dinv[ecol[e]];
}

// -------- TF32 3-split tensor-core GEMM, packed hi/lo float2 operands --------
// C = A'@B (+bias), A' = bnfuse ? lrelu(bnA[k]*A + bnC[k]) : A
// optional out2 = bias2 + selfc[r]*C
#define BM 128
#define BN 128
#define BKT 16
#define SST2 132   // float2 stride; 132 % 16 == 4 -> conflict-free quad frag reads

__device__ __forceinline__ void tf32_split(float x, float &hi, float &lo) {
    unsigned h;
    asm("cvt.rna.tf32.f32 %0, %1;" : "=r"(h) : "f"(x));
    float r = x - __uint_as_float(h);
    unsigned l;
    asm("cvt.rna.tf32.f32 %0, %1;" : "=r"(l) : "f"(r));
    hi = __uint_as_float(h); lo = __uint_as_float(l);
}

__device__ __forceinline__ void mma_tf32(float c[4], const unsigned a[4],
                                         unsigned b0, unsigned b1) {
    asm("mma.sync.aligned.m16n8k8.row.col.f32.tf32.tf32.f32 "
        "{%0,%1,%2,%3},{%4,%5,%6,%7},{%8,%9},{%0,%1,%2,%3};"
        : "+f"(c[0]), "+f"(c[1]), "+f"(c[2]), "+f"(c[3])
        : "r"(a[0]), "r"(a[1]), "r"(a[2]), "r"(a[3]), "r"(b0), "r"(b1));
}

__global__ __launch_bounds__(256)
void gemm_tf32(const float* __restrict__ A, const float* __restrict__ B,
               const float* __restrict__ bias, float* __restrict__ C,
               const float* __restrict__ selfc, const float* __restrict__ bias2,
               float* __restrict__ out2,
               const float* __restrict__ bnA, const float* __restrict__ bnC,
               int M, int N, int K) {
    __shared__ float2 Ahl[BKT][SST2];
    __shared__ float2 Bhl[BKT][SST2];

    int tid  = threadIdx.x;
    int lane = tid & 31;
    int warp = tid >> 5;
    int warpM = warp & 3;    // 4 warps down M: 32 rows each
    int warpN = warp >> 2;   // 2 warps across N: 64 cols each
    int bm = blockIdx.y * BM;
    int bn = blockIdx.x * BN;

    float acc[2][8][4];
#pragma unroll
    for (int i = 0; i < 2; i++)
#pragma unroll
        for (int j = 0; j < 8; j++)
#pragma unroll
            for (int r = 0; r < 4; r++) acc[i][j][r] = 0.0f;

    int arow = tid >> 1;            // 0..127
    int ac0  = (tid & 1) * 8;       // 0 or 8
    int br   = tid >> 5;            // 0..7 (rows br and br+8)
    int bc0  = (tid & 31) * 4;      // 0..124

    for (int k0 = 0; k0 < K; k0 += BKT) {
        // ---- A tile (128 x 16): load row, optional BN+lrelu, split, store [k][m] ----
        float av[8];
        if (bm + arow < M) {
            const float* ap = A + (long long)(bm + arow) * K + k0 + ac0;
            float4 a0 = *reinterpret_cast<const float4*>(ap);
            float4 a1 = *reinterpret_cast<const float4*>(ap + 4);
            av[0] = a0.x; av[1] = a0.y; av[2] = a0.z; av[3] = a0.w;
            av[4] = a1.x; av[5] = a1.y; av[6] = a1.z; av[7] = a1.w;
        } else {
#pragma unroll
            for (int j = 0; j < 8; j++) av[j] = 0.0f;
        }
        if (bnA) {
#pragma unroll
            for (int j = 0; j < 8; j++) {
                float t = fmaf(bnA[k0 + ac0 + j], av[j], bnC[k0 + ac0 + j]);
                av[j] = t > 0.f ? t : SLOPE * t;
            }
        }
#pragma unroll
        for (int j = 0; j < 8; j++) {
            float h, l;
            tf32_split(av[j], h, l);
            Ahl[ac0 + j][arow] = make_float2(h, l);
        }
        // ---- B tile (16 x 128): two rows (br, br+8), 4 cols each ----
        {
            const float* bp0 = B + (long long)(k0 + br) * N + bn + bc0;
            const float* bp1 = B + (long long)(k0 + br + 8) * N + bn + bc0;
            float4 b0 = *reinterpret_cast<const float4*>(bp0);
            float4 b1 = *reinterpret_cast<const float4*>(bp1);
            float h0, l0, h1, l1, h2, l2, h3, l3;
            tf32_split(b0.x, h0, l0); tf32_split(b0.y, h1, l1);
            tf32_split(b0.z, h2, l2); tf32_split(b0.w, h3, l3);
            float4* d0 = reinterpret_cast<float4*>(&Bhl[br][bc0]);
            d0[0] = make_float4(h0, l0, h1, l1);
            d0[1] = make_float4(h2, l2, h3, l3);
            tf32_split(b1.x, h0, l0); tf32_split(b1.y, h1, l1);
            tf32_split(b1.z, h2, l2); tf32_split(b1.w, h3, l3);
            float4* d1 = reinterpret_cast<float4*>(&Bhl[br + 8][bc0]);
            d1[0] = make_float4(h0, l0, h1, l1);
            d1[1] = make_float4(h2, l2, h3, l3);
        }
        __syncthreads();

#pragma unroll
        for (int kk = 0; kk < BKT; kk += 8) {
            int kc = kk + (lane & 3);
            int r0 = warpM * 32 + (lane >> 2);
            unsigned ahi[2][4], alo[2][4];
#pragma unroll
            for (int mt = 0; mt < 2; mt++) {
                int r = r0 + mt * 16;
                float2 a00 = Ahl[kc][r];
                float2 a01 = Ahl[kc][r + 8];
                float2 a10 = Ahl[kc + 4][r];
                float2 a11 = Ahl[kc + 4][r + 8];
                ahi[mt][0] = __float_as_uint(a00.x); alo[mt][0] = __float_as_uint(a00.y);
                ahi[mt][1] = __float_as_uint(a01.x); alo[mt][1] = __float_as_uint(a01.y);
                ahi[mt][2] = __float_as_uint(a10.x); alo[mt][2] = __float_as_uint(a10.y);
                ahi[mt][3] = __float_as_uint(a11.x); alo[mt][3] = __float_as_uint(a11.y);
            }
            int kr = kk + (lane & 3);
            int cb = warpN * 64 + (lane >> 2);
#pragma unroll
            for (int nt = 0; nt < 8; nt++) {
                int c = cb + nt * 8;
                float2 bp0 = Bhl[kr][c];
                float2 bp1 = Bhl[kr + 4][c];
                unsigned bh0 = __float_as_uint(bp0.x), bl0 = __float_as_uint(bp0.y);
                unsigned bh1 = __float_as_uint(bp1.x), bl1 = __float_as_uint(bp1.y);
#pragma unroll
                for (int mt = 0; mt < 2; mt++) {
                    mma_tf32(acc[mt][nt], ahi[mt], bh0, bh1);
                    mma_tf32(acc[mt][nt], ahi[mt], bl0, bl1);
                    mma_tf32(acc[mt][nt], alo[mt], bh0, bh1);
                }
            }
        }
        __syncthreads();
    }

    // ---- epilogue ----
#pragma unroll
    for (int mt = 0; mt < 2; mt++) {
#pragma unroll
        for (int half = 0; half < 2; half++) {
            int row = bm + warpM * 32 + mt * 16 + (lane >> 2) + half * 8;
            if (row >= M) continue;
            float sc = out2 ? selfc[row] : 0.0f;
#pragma unroll
            for (int nt = 0; nt < 8; nt++) {
                int col = bn + warpN * 64 + nt * 8 + (lane & 3) * 2;
                float v0 = acc[mt][nt][half * 2 + 0];
                float v1 = acc[mt][nt][half * 2 + 1];
                if (bias) { v0 += bias[col]; v1 += bias[col + 1]; }
                *reinterpret_cast<float2*>(C + (long long)row * N + col) =
                    make_float2(v0, v1);
                if (out2) {
                    float2 o = make_float2(bias2[col] + v0 * sc,
                                           bias2[col + 1] + v1 * sc);
                    *reinterpret_cast<float2*>(out2 + (long long)row * N + col) = o;
                }
            }
        }
    }
}

// -------- edge scatter: out[col] += norm * h[row] --------
__global__ void agg_edges_kernel(const float* __restrict__ h,
                                 const int* __restrict__ erow,
                                 const int* __restrict__ ecol,
                                 float* __restrict__ out) {
    long long gid = (long long)blockIdx.x * blockDim.x + threadIdx.x;
    int e = (int)(gid >> 7);
    int c4 = (int)(gid & 127);
    if (e >= EE) return;
    int r = erow[e];
    int c = ecol[e];
    float nm = g_norm[e];
    float4 v = *reinterpret_cast<const float4*>(h + (long long)r * HH + c4 * 4);
    float* dst = out + (long long)c * HH + c4 * 4;
    asm volatile("red.global.add.v4.f32 [%0], {%1, %2, %3, %4};"
                 :: "l"(dst), "f"(v.x * nm), "f"(v.y * nm), "f"(v.z * nm), "f"(v.w * nm)
                 : "memory");
}

// -------- batchnorm --------
__global__ void bn_stats_kernel(const float* __restrict__ X, float* __restrict__ sum,
                                float* __restrict__ sumsq) {
    int f = threadIdx.x;
    float s = 0.f, s2 = 0.f;
    for (int r = blockIdx.x; r < NN; r += gridDim.x) {
        float v = X[(long long)r * HH + f];
        s += v;
        s2 += v * v;
    }
    atomicAdd(&sum[f], s);
    atomicAdd(&sumsq[f], s2);
}

__global__ void bn_coef_kernel(const float* __restrict__ sum, const float* __restrict__ sumsq,
                               const float* __restrict__ g, const float* __restrict__ beta) {
    int f = threadIdx.x;
    float invN = 1.0f / (float)NN;
    float mu = sum[f] * invN;
    float var = fmaxf(sumsq[f] * invN - mu * mu, 0.0f);
    float s = g[f] * rsqrtf(var + EPS);
    g_bna[f] = s;
    g_bnc[f] = beta[f] - s * mu;
}

// -------- fused BN-apply + LeakyReLU + segment-max pool (layer 2) --------
__global__ void bn_pool_kernel(const float* __restrict__ X, const int* __restrict__ batch) {
    long long i4 = (long long)blockIdx.x * blockDim.x + threadIdx.x;
    long long base = i4 * 4;
    if (base >= (long long)NN * HH) return;
    int node = (int)(base >> 9);
    int f = (int)(base & 511);
    int grp = batch[node];
    float4 v = *reinterpret_cast<const float4*>(X + base);
    float4 a = *reinterpret_cast<const float4*>(g_bna + f);
    float4 c = *reinterpret_cast<const float4*>(g_bnc + f);
    float o[4];
    o[0] = fmaf(a.x, v.x, c.x); o[1] = fmaf(a.y, v.y, c.y);
    o[2] = fmaf(a.z, v.z, c.z); o[3] = fmaf(a.w, v.w, c.w);
    unsigned* dst = &g_keys[(long long)grp * HH + f];
#pragma unroll
    for (int j = 0; j < 4; j++) {
        float ov = o[j] > 0.f ? o[j] : SLOPE * o[j];
        unsigned u = __float_as_uint(ov);
        u = (u & 0x80000000u) ? ~u : (u | 0x80000000u);
        atomicMax(&dst[j], u);
    }
}

__global__ void pool_decode_kernel() {
    long long i = (long long)blockIdx.x * blockDim.x + threadIdx.x;
    if (i >= (long long)GG * HH) return;
    unsigned k = g_keys[i];
    float v;
    if (k == 0u) {
        v = 0.0f;
    } else {
        unsigned u = (k & 0x80000000u) ? (k & 0x7fffffffu) : ~k;
        v = __uint_as_float(u);
    }
    g_pooled[i] = v;
}

// -------- host launch --------
extern "C" void kernel_launch(void* const* d_in, const int* in_sizes, int n_in,
                              void* d_out, int out_size) {
    const float* x      = (const float*)d_in[0];
    const int*   ei     = (const int*)d_in[1];
    const int*   bt     = (const int*)d_in[2];
    const float* W1     = (const float*)d_in[3];
    const float* b1     = (const float*)d_in[4];
    const float* g1     = (const float*)d_in[5];
    const float* beta1  = (const float*)d_in[6];
    const float* W2     = (const float*)d_in[7];
    const float* b2     = (const float*)d_in[8];
    const float* g2     = (const float*)d_in[9];
    const float* beta2  = (const float*)d_in[10];
    const float* Wf     = (const float*)d_in[11];
    const float* bf     = (const float*)d_in[12];
    float* out = (float*)d_out;

    const int* erow = ei;
    const int* ecol = ei + EE;

    float *buf1, *buf2, *buf3, *pooled, *stats, *selfc, *bna, *bnc;
    cudaGetSymbolAddress((void**)&buf1, g_buf1);
    cudaGetSymbolAddress((void**)&buf2, g_buf2);
    cudaGetSymbolAddress((void**)&buf3, g_buf3);
    cudaGetSymbolAddress((void**)&pooled, g_pooled);
    cudaGetSymbolAddress((void**)&stats, g_stats);
    cudaGetSymbolAddress((void**)&selfc, g_selfc);
    cudaGetSymbolAddress((void**)&bna, g_bna);
    cudaGetSymbolAddress((void**)&bnc, g_bnc);

    const int T = 256;
    init_kernel<<<(GG * HH + T - 1) / T, T>>>();
    count_deg_kernel<<<(EE + T - 1) / T, T>>>(ecol);
    dinv_kernel<<<(NN + T - 1) / T, T>>>();
    edge_norm_kernel<<<(EE + T - 1) / T, T>>>(erow, ecol);

    long long elems = (long long)NN * HH;
    int blk_elem4 = (int)((elems / 4 + T - 1) / T);
    int blk_edges = (int)(((long long)EE * 128 + T - 1) / T);

    // ---- layer 1: GEMM (h1 -> buf1, fused pre-agg b1+selfc*h1 -> buf2) ----
    {
        dim3 grid(HH / BN, (NN + BM - 1) / BM);
        gemm_tf32<<<grid, 256>>>(x, W1, nullptr, buf1, selfc, b1, buf2,
                                 nullptr, nullptr, NN, HH, DINF);
    }
    agg_edges_kernel<<<blk_edges, T>>>(buf1, erow, ecol, buf2);
    bn_stats_kernel<<<1024, HH>>>(buf2, stats + 0, stats + HH);
    bn_coef_kernel<<<1, HH>>>(stats + 0, stats + HH, g1, beta1);

    // ---- layer 2: GEMM with fused BN1+lrelu on A-load ----
    // A = buf2 (raw agg), C = buf1 (h2), out2 = buf3 (b2 + selfc*h2)
    {
        dim3 grid(HH / BN, (NN + BM - 1) / BM);
        gemm_tf32<<<grid, 256>>>(buf2, W2, nullptr, buf1, selfc, b2, buf3,
                                 bna, bnc, NN, HH, HH);
    }
    agg_edges_kernel<<<blk_edges, T>>>(buf1, erow, ecol, buf3);
    bn_stats_kernel<<<1024, HH>>>(buf3, stats + 2 * HH, stats + 3 * HH);
    bn_coef_kernel<<<1, HH>>>(stats + 2 * HH, stats + 3 * HH, g2, beta2);
    bn_pool_kernel<<<blk_elem4, T>>>(buf3, bt);

    // ---- pool decode + final linear ----
    pool_decode_kernel<<<(GG * HH + T - 1) / T, T>>>();
    {
        dim3 grid(OUTC / BN, (GG + BM - 1) / BM);
        gemm_tf32<<<grid, 256>>>(pooled, Wf, bf, out, nullptr, nullptr, nullptr,
                                 nullptr, nullptr, GG, OUTC, HH);
    }
}

// round 8
// speedup vs baseline: 2.2271x; 1.4418x over previous
#include <cuda_runtime.h>
#include <cuda_fp16.h>
#include <math.h>

#define NN   100000
#define EE   300000
#define DINF 128
#define HH   512
#define GG   4096
#define OUTC 256
#define SLOPE 0.01f
#define EPS   1e-5f

// -------- scratch (device globals: allocation-free, 256B aligned) --------
__device__ __align__(256) float    g_deg[NN];
__device__ __align__(256) float    g_dinv[NN];
__device__ __align__(256) float    g_selfc[NN];
__device__ __align__(256) float    g_norm[EE];
__device__ __align__(256) float    g_buf1[(size_t)NN * HH];
__device__ __align__(256) float    g_buf2[(size_t)NN * HH];
__device__ __align__(256) float    g_buf3[(size_t)NN * HH];
__device__ __align__(256) unsigned g_keys[(size_t)GG * HH];
__device__ __align__(256) float    g_pooled[(size_t)GG * HH];
__device__ __align__(256) float    g_stats[4 * HH];
__device__ __align__(256) float    g_bna[HH];
__device__ __align__(256) float    g_bnc[HH];

// -------- init --------
__global__ void init_kernel() {
    int i = blockIdx.x * blockDim.x + threadIdx.x;
    if (i < NN) g_deg[i] = 2.0f;
    if (i < GG * HH) g_keys[i] = 0u;
    if (i < 4 * HH) g_stats[i] = 0.0f;
}

__global__ void count_deg_kernel(const int* __restrict__ ecol) {
    int e = blockIdx.x * blockDim.x + threadIdx.x;
    if (e < EE) atomicAdd(&g_deg[ecol[e]], 1.0f);
}

__global__ void dinv_kernel() {
    int i = blockIdx.x * blockDim.x + threadIdx.x;
    if (i < NN) {
        float d = g_deg[i];
        float di = rsqrtf(d);
        g_dinv[i] = di;
        g_selfc[i] = 2.0f * di * di;
    }
}

__global__ void edge_norm_kernel(const int* __restrict__ erow,
                                 const int* __restrict__ ecol) {
    int e = blockIdx.x * blockDim.x + threadIdx.x;
    if (e < EE) g_norm[e] = g_dinv[erow[e]] * g_dinv[ecol[e]];
}

// -------- FP16 2-split (3-product) tensor-core GEMM, ldmatrix operands --------
// C = A'@B (+bias), A' = bnfuse ? lrelu(bnA[k]*A + bnC[k]) : A
// optional out2 = bias2 + selfc[r]*C
#define BM 128
#define BN 128
#define BKT 32
#define ASTR 56     // A smem stride (halves): 112B rows, conflict-free LDSM, 16B aligned
#define BSTR 136    // B smem stride (halves): 272B rows, conflict-free LDSM, 16B aligned

__device__ __forceinline__ void f16_split(float x, __half &hi, __half &lo) {
    __half h = __float2half_rn(x);
    hi = h;
    lo = __float2half_rn(x - __half2float(h));
}

__device__ __forceinline__ void mma_f16(float c[4], const unsigned a[4],
                                        unsigned b0, unsigned b1) {
    asm("mma.sync.aligned.m16n8k16.row.col.f32.f16.f16.f32 "
        "{%0,%1,%2,%3},{%4,%5,%6,%7},{%8,%9},{%0,%1,%2,%3};"
        : "+f"(c[0]), "+f"(c[1]), "+f"(c[2]), "+f"(c[3])
        : "r"(a[0]), "r"(a[1]), "r"(a[2]), "r"(a[3]), "r"(b0), "r"(b1));
}

__device__ __forceinline__ void ldsm_x4(unsigned r[4], unsigned saddr) {
    asm volatile("ldmatrix.sync.aligned.m8n8.x4.shared.b16 {%0,%1,%2,%3}, [%4];"
                 : "=r"(r[0]), "=r"(r[1]), "=r"(r[2]), "=r"(r[3]) : "r"(saddr));
}

__device__ __forceinline__ void ldsm_x2t(unsigned &r0, unsigned &r1, unsigned saddr) {
    asm volatile("ldmatrix.sync.aligned.m8n8.x2.trans.shared.b16 {%0,%1}, [%2];"
                 : "=r"(r0), "=r"(r1) : "r"(saddr));
}

__global__ __launch_bounds__(256)
void gemm_f16s(const float* __restrict__ A, const float* __restrict__ B,
               const float* __restrict__ bias, float* __restrict__ C,
               const float* __restrict__ selfc, const float* __restrict__ bias2,
               float* __restrict__ out2,
               const float* __restrict__ bnA, const float* __restrict__ bnC,
               int M, int N, int K) {
    __shared__ __align__(16) __half Ah[BM][ASTR], Al[BM][ASTR];
    __shared__ __align__(16) __half Bh[BKT][BSTR], Bl[BKT][BSTR];

    int tid  = threadIdx.x;
    int lane = tid & 31;
    int warp = tid >> 5;
    int warpM = warp & 3;    // 4 warps down M (32 rows each)
    int warpN = warp >> 2;   // 2 warps across N (64 cols each)
    int bm = blockIdx.y * BM;
    int bn = blockIdx.x * BN;

    float acc[2][8][4];
#pragma unroll
    for (int i = 0; i < 2; i++)
#pragma unroll
        for (int j = 0; j < 8; j++)
#pragma unroll
            for (int r = 0; r < 4; r++) acc[i][j][r] = 0.0f;

    int arow = tid >> 1;            // 0..127
    int ak0  = (tid & 1) * 16;      // 0 or 16
    int bkr  = tid >> 3;            // 0..31
    int bc0  = (tid & 7) * 16;      // 0..112

    unsigned a_base_h = (unsigned)__cvta_generic_to_shared(&Ah[0][0]);
    unsigned a_base_l = (unsigned)__cvta_generic_to_shared(&Al[0][0]);
    unsigned b_base_h = (unsigned)__cvta_generic_to_shared(&Bh[0][0]);
    unsigned b_base_l = (unsigned)__cvta_generic_to_shared(&Bl[0][0]);

    for (int k0 = 0; k0 < K; k0 += BKT) {
        // ---- A tile (BM x BKT): load 16 floats/thread, opt BN+lrelu, split ----
        {
            bool inM = (bm + arow < M);
            const float* ap = A + (long long)(bm + arow) * K + k0 + ak0;
#pragma unroll
            for (int q = 0; q < 4; q++) {
                float4 av = inM ? *reinterpret_cast<const float4*>(ap + q * 4)
                                : make_float4(0.f, 0.f, 0.f, 0.f);
                float vv[4] = {av.x, av.y, av.z, av.w};
#pragma unroll
                for (int j = 0; j < 4; j++) {
                    int kc = ak0 + q * 4 + j;
                    float t = vv[j];
                    if (bnA) {
                        t = fmaf(bnA[k0 + kc], t, bnC[k0 + kc]);
                        t = t > 0.f ? t : SLOPE * t;
                    }
                    __half h, l;
                    f16_split(t, h, l);
                    Ah[arow][kc] = h;
                    Al[arow][kc] = l;
                }
            }
        }
        // ---- B tile (BKT x BN): row bkr, 16 cols from bc0 ----
        {
            const float* bp = B + (long long)(k0 + bkr) * N + bn + bc0;
#pragma unroll
            for (int q = 0; q < 4; q++) {
                float4 bv = *reinterpret_cast<const float4*>(bp + q * 4);
                float vv[4] = {bv.x, bv.y, bv.z, bv.w};
#pragma unroll
                for (int j = 0; j < 4; j++) {
                    __half h, l;
                    f16_split(vv[j], h, l);
                    Bh[bkr][bc0 + q * 4 + j] = h;
                    Bl[bkr][bc0 + q * 4 + j] = l;
                }
            }
        }
        __syncthreads();

#pragma unroll
        for (int kk = 0; kk < BKT; kk += 16) {
            // A fragments: per mt, hi & lo via ldmatrix.x4
            unsigned ahi[2][4], alo[2][4];
            int lr = lane & 15;
            int acol = kk + ((lane >> 4) << 3);
#pragma unroll
            for (int mt = 0; mt < 2; mt++) {
                int r = warpM * 32 + mt * 16 + lr;
                unsigned off = (unsigned)(r * ASTR + acol) * 2u;
                ldsm_x4(ahi[mt], a_base_h + off);
                ldsm_x4(alo[mt], a_base_l + off);
            }
            int kr = kk + (lane & 15);
#pragma unroll
            for (int nt = 0; nt < 8; nt++) {
                int n0 = warpN * 64 + nt * 8;
                unsigned boff = (unsigned)(kr * BSTR + n0) * 2u;
                unsigned bh0, bh1, bl0, bl1;
                ldsm_x2t(bh0, bh1, b_base_h + boff);
                ldsm_x2t(bl0, bl1, b_base_l + boff);
#pragma unroll
                for (int mt = 0; mt < 2; mt++) {
                    mma_f16(acc[mt][nt], ahi[mt], bh0, bh1);
                    mma_f16(acc[mt][nt], ahi[mt], bl0, bl1);
                    mma_f16(acc[mt][nt], alo[mt], bh0, bh1);
                }
            }
        }
        __syncthreads();
    }

    // ---- epilogue ----
#pragma unroll
    for (int mt = 0; mt < 2; mt++) {
#pragma unroll
        for (int half = 0; half < 2; half++) {
            int row = bm + warpM * 32 + mt * 16 + (lane >> 2) + half * 8;
            if (row >= M) continue;
            float sc = out2 ? selfc[row] : 0.0f;
#pragma unroll
            for (int nt = 0; nt < 8; nt++) {
                int col = bn + warpN * 64 + nt * 8 + (lane & 3) * 2;
                float v0 = acc[mt][nt][half * 2 + 0];
                float v1 = acc[mt][nt][half * 2 + 1];
                if (bias) { v0 += bias[col]; v1 += bias[col + 1]; }
                *reinterpret_cast<float2*>(C + (long long)row * N + col) =
                    make_float2(v0, v1);
                if (out2) {
                    float2 o = make_float2(bias2[col] + v0 * sc,
                                           bias2[col + 1] + v1 * sc);
                    *reinterpret_cast<float2*>(out2 + (long long)row * N + col) = o;
                }
            }
        }
    }
}

// -------- edge scatter: out[col] += norm * h[row] --------
__global__ void agg_edges_kernel(const float* __restrict__ h,
                                 const int* __restrict__ erow,
                                 const int* __restrict__ ecol,
                                 float* __restrict__ out) {
    long long gid = (long long)blockIdx.x * blockDim.x + threadIdx.x;
    int e = (int)(gid >> 7);
    int c4 = (int)(gid & 127);
    if (e >= EE) return;
    int r = erow[e];
    int c = ecol[e];
    float nm = g_norm[e];
    float4 v = *reinterpret_cast<const float4*>(h + (long long)r * HH + c4 * 4);
    float* dst = out + (long long)c * HH + c4 * 4;
    asm volatile("red.global.add.v4.f32 [%0], {%1, %2, %3, %4};"
                 :: "l"(dst), "f"(v.x * nm), "f"(v.y * nm), "f"(v.z * nm), "f"(v.w * nm)
                 : "memory");
}

// -------- batchnorm --------
__global__ void bn_stats_kernel(const float* __restrict__ X, float* __restrict__ sum,
                                float* __restrict__ sumsq) {
    int f = threadIdx.x;
    float s = 0.f, s2 = 0.f;
    for (int r = blockIdx.x; r < NN; r += gridDim.x) {
        float v = X[(long long)r * HH + f];
        s += v;
        s2 += v * v;
    }
    atomicAdd(&sum[f], s);
    atomicAdd(&sumsq[f], s2);
}

__global__ void bn_coef_kernel(const float* __restrict__ sum, const float* __restrict__ sumsq,
                               const float* __restrict__ g, const float* __restrict__ beta) {
    int f = threadIdx.x;
    float invN = 1.0f / (float)NN;
    float mu = sum[f] * invN;
    float var = fmaxf(sumsq[f] * invN - mu * mu, 0.0f);
    float s = g[f] * rsqrtf(var + EPS);
    g_bna[f] = s;
    g_bnc[f] = beta[f] - s * mu;
}

// -------- fused BN-apply + LeakyReLU + segment-max pool (layer 2) --------
__global__ void bn_pool_kernel(const float* __restrict__ X, const int* __restrict__ batch) {
    long long i4 = (long long)blockIdx.x * blockDim.x + threadIdx.x;
    long long base = i4 * 4;
    if (base >= (long long)NN * HH) return;
    int node = (int)(base >> 9);
    int f = (int)(base & 511);
    int grp = batch[node];
    float4 v = *reinterpret_cast<const float4*>(X + base);
    float4 a = *reinterpret_cast<const float4*>(g_bna + f);
    float4 c = *reinterpret_cast<const float4*>(g_bnc + f);
    float o[4];
    o[0] = fmaf(a.x, v.x, c.x); o[1] = fmaf(a.y, v.y, c.y);
    o[2] = fmaf(a.z, v.z, c.z); o[3] = fmaf(a.w, v.w, c.w);
    unsigned* dst = &g_keys[(long long)grp * HH + f];
#pragma unroll
    for (int j = 0; j < 4; j++) {
        float ov = o[j] > 0.f ? o[j] : SLOPE * o[j];
        unsigned u = __float_as_uint(ov);
        u = (u & 0x80000000u) ? ~u : (u | 0x80000000u);
        atomicMax(&dst[j], u);
    }
}

__global__ void pool_decode_kernel() {
    long long i = (long long)blockIdx.x * blockDim.x + threadIdx.x;
    if (i >= (long long)GG * HH) return;
    unsigned k = g_keys[i];
    float v;
    if (k == 0u) {
        v = 0.0f;
    } else {
        unsigned u = (k & 0x80000000u) ? (k & 0x7fffffffu) : ~k;
        v = __uint_as_float(u);
    }
    g_pooled[i] = v;
}

// -------- host launch --------
extern "C" void kernel_launch(void* const* d_in, const int* in_sizes, int n_in,
                              void* d_out, int out_size) {
    const float* x      = (const float*)d_in[0];
    const int*   ei     = (const int*)d_in[1];
    const int*   bt     = (const int*)d_in[2];
    const float* W1     = (const float*)d_in[3];
    const float* b1     = (const float*)d_in[4];
    const float* g1     = (const float*)d_in[5];
    const float* beta1  = (const float*)d_in[6];
    const float* W2     = (const float*)d_in[7];
    const float* b2     = (const float*)d_in[8];
    const float* g2     = (const float*)d_in[9];
    const float* beta2  = (const float*)d_in[10];
    const float* Wf     = (const float*)d_in[11];
    const float* bf     = (const float*)d_in[12];
    float* out = (float*)d_out;

    const int* erow = ei;
    const int* ecol = ei + EE;

    float *buf1, *buf2, *buf3, *pooled, *stats, *selfc, *bna, *bnc;
    cudaGetSymbolAddress((void**)&buf1, g_buf1);
    cudaGetSymbolAddress((void**)&buf2, g_buf2);
    cudaGetSymbolAddress((void**)&buf3, g_buf3);
    cudaGetSymbolAddress((void**)&pooled, g_pooled);
    cudaGetSymbolAddress((void**)&stats, g_stats);
    cudaGetSymbolAddress((void**)&selfc, g_selfc);
    cudaGetSymbolAddress((void**)&bna, g_bna);
    cudaGetSymbolAddress((void**)&bnc, g_bnc);

    const int T = 256;
    init_kernel<<<(GG * HH + T - 1) / T, T>>>();
    count_deg_kernel<<<(EE + T - 1) / T, T>>>(ecol);
    dinv_kernel<<<(NN + T - 1) / T, T>>>();
    edge_norm_kernel<<<(EE + T - 1) / T, T>>>(erow, ecol);

    long long elems = (long long)NN * HH;
    int blk_elem4 = (int)((elems / 4 + T - 1) / T);
    int blk_edges = (int)(((long long)EE * 128 + T - 1) / T);

    // ---- layer 1: GEMM (h1 -> buf1, fused pre-agg b1+selfc*h1 -> buf2) ----
    {
        dim3 grid(HH / BN, (NN + BM - 1) / BM);
        gemm_f16s<<<grid, 256>>>(x, W1, nullptr, buf1, selfc, b1, buf2,
                                 nullptr, nullptr, NN, HH, DINF);
    }
    agg_edges_kernel<<<blk_edges, T>>>(buf1, erow, ecol, buf2);
    bn_stats_kernel<<<1024, HH>>>(buf2, stats + 0, stats + HH);
    bn_coef_kernel<<<1, HH>>>(stats + 0, stats + HH, g1, beta1);

    // ---- layer 2: GEMM with fused BN1+lrelu on A-load ----
    {
        dim3 grid(HH / BN, (NN + BM - 1) / BM);
        gemm_f16s<<<grid, 256>>>(buf2, W2, nullptr, buf1, selfc, b2, buf3,
                                 bna, bnc, NN, HH, HH);
    }
    agg_edges_kernel<<<blk_edges, T>>>(buf1, erow, ecol, buf3);
    bn_stats_kernel<<<1024, HH>>>(buf3, stats + 2 * HH, stats + 3 * HH);
    bn_coef_kernel<<<1, HH>>>(stats + 2 * HH, stats + 3 * HH, g2, beta2);
    bn_pool_kernel<<<blk_elem4, T>>>(buf3, bt);

    // ---- pool decode + final linear ----
    pool_decode_kernel<<<(GG * HH + T - 1) / T, T>>>();
    {
        dim3 grid(OUTC / BN, (GG + BM - 1) / BM);
        gemm_f16s<<<grid, 256>>>(pooled, Wf, bf, out, nullptr, nullptr, nullptr,
                                 nullptr, nullptr, GG, OUTC, HH);
    }
}

// round 9
// speedup vs baseline: 2.4734x; 1.1106x over previous
#include <cuda_runtime.h>
#include <cuda_fp16.h>
#include <math.h>

#define NN   100000
#define EE   300000
#define DINF 128
#define HH   512
#define GG   4096
#define OUTC 256
#define SLOPE 0.01f
#define EPS   1e-5f

// -------- scratch (device globals: allocation-free, 256B aligned) --------
__device__ __align__(256) float    g_deg[NN];
__device__ __align__(256) float    g_dinv[NN];
__device__ __align__(256) float    g_selfc[NN];
__device__ __align__(256) float    g_norm[EE];
__device__ __align__(256) float    g_buf1[(size_t)NN * HH];   // P1
__device__ __align__(256) float    g_buf2[(size_t)NN * HH];   // Xa (N*128) then Za (N*512)
__device__ __align__(256) float    g_buf3[(size_t)NN * HH];   // P2
__device__ __align__(256) unsigned g_keys[(size_t)GG * HH];
__device__ __align__(256) float    g_pooled[(size_t)GG * HH];
__device__ __align__(256) float    g_stats[4 * HH];
__device__ __align__(256) float    g_bna[HH];
__device__ __align__(256) float    g_bnc[HH];

// -------- init --------
__global__ void init_kernel() {
    int i = blockIdx.x * blockDim.x + threadIdx.x;
    if (i < NN) g_deg[i] = 2.0f;
    if (i < GG * HH) g_keys[i] = 0u;
    if (i < 4 * HH) g_stats[i] = 0.0f;
}

__global__ void count_deg_kernel(const int* __restrict__ ecol) {
    int e = blockIdx.x * blockDim.x + threadIdx.x;
    if (e < EE) atomicAdd(&g_deg[ecol[e]], 1.0f);
}

__global__ void dinv_kernel() {
    int i = blockIdx.x * blockDim.x + threadIdx.x;
    if (i < NN) {
        float d = g_deg[i];
        float di = rsqrtf(d);
        g_dinv[i] = di;
        g_selfc[i] = 2.0f * di * di;
    }
}

__global__ void edge_norm_kernel(const int* __restrict__ erow,
                                 const int* __restrict__ ecol) {
    int e = blockIdx.x * blockDim.x + threadIdx.x;
    if (e < EE) g_norm[e] = g_dinv[erow[e]] * g_dinv[ecol[e]];
}

// -------- layer-1 input aggregation on X (N x 128) --------
__global__ void aggx_init_kernel(const float* __restrict__ x, float* __restrict__ xa) {
    long long i4 = (long long)blockIdx.x * blockDim.x + threadIdx.x;
    long long base = i4 * 4;
    if (base >= (long long)NN * DINF) return;
    int node = (int)(base >> 7);   // DINF=128
    float sc = g_selfc[node];
    float4 v = *reinterpret_cast<const float4*>(x + base);
    float4 o = make_float4(v.x * sc, v.y * sc, v.z * sc, v.w * sc);
    *reinterpret_cast<float4*>(xa + base) = o;
}

__global__ void aggx_edges_kernel(const float* __restrict__ x,
                                  const int* __restrict__ erow,
                                  const int* __restrict__ ecol,
                                  float* __restrict__ xa) {
    long long gid = (long long)blockIdx.x * blockDim.x + threadIdx.x;
    int e = (int)(gid >> 5);        // DINF/4 = 32 float4 per edge
    int c4 = (int)(gid & 31);
    if (e >= EE) return;
    int r = erow[e];
    int c = ecol[e];
    float nm = g_norm[e];
    float4 v = *reinterpret_cast<const float4*>(x + (long long)r * DINF + c4 * 4);
    float* dst = xa + (long long)c * DINF + c4 * 4;
    asm volatile("red.global.add.v4.f32 [%0], {%1, %2, %3, %4};"
                 :: "l"(dst), "f"(v.x * nm), "f"(v.y * nm), "f"(v.z * nm), "f"(v.w * nm)
                 : "memory");
}

// -------- FP16 2-split (3-product) tensor-core GEMM, ldmatrix operands --------
#define BM 128
#define BN 128
#define BKT 32
#define ASTR 56
#define BSTR 136

__device__ __forceinline__ void f16_split(float x, __half &hi, __half &lo) {
    __half h = __float2half_rn(x);
    hi = h;
    lo = __float2half_rn(x - __half2float(h));
}

__device__ __forceinline__ void mma_f16(float c[4], const unsigned a[4],
                                        unsigned b0, unsigned b1) {
    asm("mma.sync.aligned.m16n8k16.row.col.f32.f16.f16.f32 "
        "{%0,%1,%2,%3},{%4,%5,%6,%7},{%8,%9},{%0,%1,%2,%3};"
        : "+f"(c[0]), "+f"(c[1]), "+f"(c[2]), "+f"(c[3])
        : "r"(a[0]), "r"(a[1]), "r"(a[2]), "r"(a[3]), "r"(b0), "r"(b1));
}

__device__ __forceinline__ void ldsm_x4(unsigned r[4], unsigned saddr) {
    asm volatile("ldmatrix.sync.aligned.m8n8.x4.shared.b16 {%0,%1,%2,%3}, [%4];"
                 : "=r"(r[0]), "=r"(r[1]), "=r"(r[2]), "=r"(r[3]) : "r"(saddr));
}

__device__ __forceinline__ void ldsm_x2t(unsigned &r0, unsigned &r1, unsigned saddr) {
    asm volatile("ldmatrix.sync.aligned.m8n8.x2.trans.shared.b16 {%0,%1}, [%2];"
                 : "=r"(r0), "=r"(r1) : "r"(saddr));
}

__global__ __launch_bounds__(256)
void gemm_f16s(const float* __restrict__ A, const float* __restrict__ B,
               const float* __restrict__ bias, float* __restrict__ C,
               int M, int N, int K) {
    __shared__ __align__(16) __half Ah[BM][ASTR], Al[BM][ASTR];
    __shared__ __align__(16) __half Bh[BKT][BSTR], Bl[BKT][BSTR];

    int tid  = threadIdx.x;
    int lane = tid & 31;
    int warp = tid >> 5;
    int warpM = warp & 3;
    int warpN = warp >> 2;
    int bm = blockIdx.y * BM;
    int bn = blockIdx.x * BN;

    float acc[2][8][4];
#pragma unroll
    for (int i = 0; i < 2; i++)
#pragma unroll
        for (int j = 0; j < 8; j++)
#pragma unroll
            for (int r = 0; r < 4; r++) acc[i][j][r] = 0.0f;

    int arow = tid >> 1;
    int ak0  = (tid & 1) * 16;
    int bkr  = tid >> 3;
    int bc0  = (tid & 7) * 16;

    unsigned a_base_h = (unsigned)__cvta_generic_to_shared(&Ah[0][0]);
    unsigned a_base_l = (unsigned)__cvta_generic_to_shared(&Al[0][0]);
    unsigned b_base_h = (unsigned)__cvta_generic_to_shared(&Bh[0][0]);
    unsigned b_base_l = (unsigned)__cvta_generic_to_shared(&Bl[0][0]);

    for (int k0 = 0; k0 < K; k0 += BKT) {
        {
            bool inM = (bm + arow < M);
            const float* ap = A + (long long)(bm + arow) * K + k0 + ak0;
#pragma unroll
            for (int q = 0; q < 4; q++) {
                float4 av = inM ? *reinterpret_cast<const float4*>(ap + q * 4)
                                : make_float4(0.f, 0.f, 0.f, 0.f);
                float vv[4] = {av.x, av.y, av.z, av.w};
#pragma unroll
                for (int j = 0; j < 4; j++) {
                    int kc = ak0 + q * 4 + j;
                    __half h, l;
                    f16_split(vv[j], h, l);
                    Ah[arow][kc] = h;
                    Al[arow][kc] = l;
                }
            }
        }
        {
            const float* bp = B + (long long)(k0 + bkr) * N + bn + bc0;
#pragma unroll
            for (int q = 0; q < 4; q++) {
                float4 bv = *reinterpret_cast<const float4*>(bp + q * 4);
                float vv[4] = {bv.x, bv.y, bv.z, bv.w};
#pragma unroll
                for (int j = 0; j < 4; j++) {
                    __half h, l;
                    f16_split(vv[j], h, l);
                    Bh[bkr][bc0 + q * 4 + j] = h;
                    Bl[bkr][bc0 + q * 4 + j] = l;
                }
            }
        }
        __syncthreads();

#pragma unroll
        for (int kk = 0; kk < BKT; kk += 16) {
            unsigned ahi[2][4], alo[2][4];
            int lr = lane & 15;
            int acol = kk + ((lane >> 4) << 3);
#pragma unroll
            for (int mt = 0; mt < 2; mt++) {
                int r = warpM * 32 + mt * 16 + lr;
                unsigned off = (unsigned)(r * ASTR + acol) * 2u;
                ldsm_x4(ahi[mt], a_base_h + off);
                ldsm_x4(alo[mt], a_base_l + off);
            }
            int kr = kk + (lane & 15);
#pragma unroll
            for (int nt = 0; nt < 8; nt++) {
                int n0 = warpN * 64 + nt * 8;
                unsigned boff = (unsigned)(kr * BSTR + n0) * 2u;
                unsigned bh0, bh1, bl0, bl1;
                ldsm_x2t(bh0, bh1, b_base_h + boff);
                ldsm_x2t(bl0, bl1, b_base_l + boff);
#pragma unroll
                for (int mt = 0; mt < 2; mt++) {
                    mma_f16(acc[mt][nt], ahi[mt], bh0, bh1);
                    mma_f16(acc[mt][nt], ahi[mt], bl0, bl1);
                    mma_f16(acc[mt][nt], alo[mt], bh0, bh1);
                }
            }
        }
        __syncthreads();
    }

#pragma unroll
    for (int mt = 0; mt < 2; mt++) {
#pragma unroll
        for (int half = 0; half < 2; half++) {
            int row = bm + warpM * 32 + mt * 16 + (lane >> 2) + half * 8;
            if (row >= M) continue;
#pragma unroll
            for (int nt = 0; nt < 8; nt++) {
                int col = bn + warpN * 64 + nt * 8 + (lane & 3) * 2;
                float v0 = acc[mt][nt][half * 2 + 0];
                float v1 = acc[mt][nt][half * 2 + 1];
                if (bias) { v0 += bias[col]; v1 += bias[col + 1]; }
                *reinterpret_cast<float2*>(C + (long long)row * N + col) =
                    make_float2(v0, v1);
            }
        }
    }
}

// -------- batchnorm stats/coefs --------
__global__ void bn_stats_kernel(const float* __restrict__ X, float* __restrict__ sum,
                                float* __restrict__ sumsq) {
    int f = threadIdx.x;
    float s = 0.f, s2 = 0.f;
    for (int r = blockIdx.x; r < NN; r += gridDim.x) {
        float v = X[(long long)r * HH + f];
        s += v;
        s2 += v * v;
    }
    atomicAdd(&sum[f], s);
    atomicAdd(&sumsq[f], s2);
}

__global__ void bn_coef_kernel(const float* __restrict__ sum, const float* __restrict__ sumsq,
                               const float* __restrict__ g, const float* __restrict__ beta) {
    int f = threadIdx.x;
    float invN = 1.0f / (float)NN;
    float mu = sum[f] * invN;
    float var = fmaxf(sumsq[f] * invN - mu * mu, 0.0f);
    float s = g[f] * rsqrtf(var + EPS);
    g_bna[f] = s;
    g_bnc[f] = beta[f] - s * mu;
}

// -------- layer-2 aggregation on Z = lrelu(bn1(P1)), BN fused inline --------
__global__ void aggz_init_kernel(const float* __restrict__ P1, float* __restrict__ za) {
    long long i4 = (long long)blockIdx.x * blockDim.x + threadIdx.x;
    long long base = i4 * 4;
    if (base >= (long long)NN * HH) return;
    int node = (int)(base >> 9);
    int f = (int)(base & 511);
    float sc = g_selfc[node];
    float4 v = *reinterpret_cast<const float4*>(P1 + base);
    float4 a = *reinterpret_cast<const float4*>(g_bna + f);
    float4 c = *reinterpret_cast<const float4*>(g_bnc + f);
    float z[4];
    z[0] = fmaf(a.x, v.x, c.x); z[1] = fmaf(a.y, v.y, c.y);
    z[2] = fmaf(a.z, v.z, c.z); z[3] = fmaf(a.w, v.w, c.w);
#pragma unroll
    for (int j = 0; j < 4; j++) z[j] = (z[j] > 0.f ? z[j] : SLOPE * z[j]) * sc;
    *reinterpret_cast<float4*>(za + base) = make_float4(z[0], z[1], z[2], z[3]);
}

__global__ void aggz_edges_kernel(const float* __restrict__ P1,
                                  const int* __restrict__ erow,
                                  const int* __restrict__ ecol,
                                  float* __restrict__ za) {
    long long gid = (long long)blockIdx.x * blockDim.x + threadIdx.x;
    int e = (int)(gid >> 7);
    int c4 = (int)(gid & 127);
    if (e >= EE) return;
    int r = erow[e];
    int c = ecol[e];
    float nm = g_norm[e];
    int f = c4 * 4;
    float4 v = *reinterpret_cast<const float4*>(P1 + (long long)r * HH + f);
    float4 a = *reinterpret_cast<const float4*>(g_bna + f);
    float4 cc = *reinterpret_cast<const float4*>(g_bnc + f);
    float z[4];
    z[0] = fmaf(a.x, v.x, cc.x); z[1] = fmaf(a.y, v.y, cc.y);
    z[2] = fmaf(a.z, v.z, cc.z); z[3] = fmaf(a.w, v.w, cc.w);
#pragma unroll
    for (int j = 0; j < 4; j++) z[j] = (z[j] > 0.f ? z[j] : SLOPE * z[j]) * nm;
    float* dst = za + (long long)c * HH + f;
    asm volatile("red.global.add.v4.f32 [%0], {%1, %2, %3, %4};"
                 :: "l"(dst), "f"(z[0]), "f"(z[1]), "f"(z[2]), "f"(z[3])
                 : "memory");
}

// -------- fused BN-apply + LeakyReLU + segment-max pool (layer 2) --------
__global__ void bn_pool_kernel(const float* __restrict__ X, const int* __restrict__ batch) {
    long long i4 = (long long)blockIdx.x * blockDim.x + threadIdx.x;
    long long base = i4 * 4;
    if (base >= (long long)NN * HH) return;
    int node = (int)(base >> 9);
    int f = (int)(base & 511);
    int grp = batch[node];
    float4 v = *reinterpret_cast<const float4*>(X + base);
    float4 a = *reinterpret_cast<const float4*>(g_bna + f);
    float4 c = *reinterpret_cast<const float4*>(g_bnc + f);
    float o[4];
    o[0] = fmaf(a.x, v.x, c.x); o[1] = fmaf(a.y, v.y, c.y);
    o[2] = fmaf(a.z, v.z, c.z); o[3] = fmaf(a.w, v.w, c.w);
    unsigned* dst = &g_keys[(long long)grp * HH + f];
#pragma unroll
    for (int j = 0; j < 4; j++) {
        float ov = o[j] > 0.f ? o[j] : SLOPE * o[j];
        unsigned u = __float_as_uint(ov);
        u = (u & 0x80000000u) ? ~u : (u | 0x80000000u);
        atomicMax(&dst[j], u);
    }
}

__global__ void pool_decode_kernel() {
    long long i = (long long)blockIdx.x * blockDim.x + threadIdx.x;
    if (i >= (long long)GG * HH) return;
    unsigned k = g_keys[i];
    float v;
    if (k == 0u) {
        v = 0.0f;
    } else {
        unsigned u = (k & 0x80000000u) ? (k & 0x7fffffffu) : ~k;
        v = __uint_as_float(u);
    }
    g_pooled[i] = v;
}

// -------- host launch --------
extern "C" void kernel_launch(void* const* d_in, const int* in_sizes, int n_in,
                              void* d_out, int out_size) {
    const float* x      = (const float*)d_in[0];
    const int*   ei     = (const int*)d_in[1];
    const int*   bt     = (const int*)d_in[2];
    const float* W1     = (const float*)d_in[3];
    const float* b1     = (const float*)d_in[4];
    const float* g1     = (const float*)d_in[5];
    const float* beta1  = (const float*)d_in[6];
    const float* W2     = (const float*)d_in[7];
    const float* b2     = (const float*)d_in[8];
    const float* g2     = (const float*)d_in[9];
    const float* beta2  = (const float*)d_in[10];
    const float* Wf     = (const float*)d_in[11];
    const float* bf     = (const float*)d_in[12];
    float* out = (float*)d_out;

    const int* erow = ei;
    const int* ecol = ei + EE;

    float *buf1, *buf2, *buf3, *pooled, *stats;
    cudaGetSymbolAddress((void**)&buf1, g_buf1);
    cudaGetSymbolAddress((void**)&buf2, g_buf2);
    cudaGetSymbolAddress((void**)&buf3, g_buf3);
    cudaGetSymbolAddress((void**)&pooled, g_pooled);
    cudaGetSymbolAddress((void**)&stats, g_stats);

    const int T = 256;
    init_kernel<<<(GG * HH + T - 1) / T, T>>>();
    count_deg_kernel<<<(EE + T - 1) / T, T>>>(ecol);
    dinv_kernel<<<(NN + T - 1) / T, T>>>();
    edge_norm_kernel<<<(EE + T - 1) / T, T>>>(erow, ecol);

    long long elemsH = (long long)NN * HH;
    long long elemsX = (long long)NN * DINF;
    int blk_h4 = (int)((elemsH / 4 + T - 1) / T);
    int blk_x4 = (int)((elemsX / 4 + T - 1) / T);
    int blk_xe = (int)(((long long)EE * 32 + T - 1) / T);
    int blk_ze = (int)(((long long)EE * 128 + T - 1) / T);

    // ---- layer 1: aggregate X (N x 128), then GEMM ----
    aggx_init_kernel<<<blk_x4, T>>>(x, buf2);
    aggx_edges_kernel<<<blk_xe, T>>>(x, erow, ecol, buf2);
    {
        dim3 grid(HH / BN, (NN + BM - 1) / BM);
        gemm_f16s<<<grid, 256>>>(buf2, W1, b1, buf1, NN, HH, DINF);   // P1
    }
    bn_stats_kernel<<<1024, HH>>>(buf1, stats + 0, stats + HH);
    bn_coef_kernel<<<1, HH>>>(stats + 0, stats + HH, g1, beta1);

    // ---- layer 2: aggregate Z = lrelu(bn1(P1)) (BN inline), then GEMM ----
    aggz_init_kernel<<<blk_h4, T>>>(buf1, buf2);
    aggz_edges_kernel<<<blk_ze, T>>>(buf1, erow, ecol, buf2);
    {
        dim3 grid(HH / BN, (NN + BM - 1) / BM);
        gemm_f16s<<<grid, 256>>>(buf2, W2, b2, buf3, NN, HH, HH);     // P2
    }
    bn_stats_kernel<<<1024, HH>>>(buf3, stats + 2 * HH, stats + 3 * HH);
    bn_coef_kernel<<<1, HH>>>(stats + 2 * HH, stats + 3 * HH, g2, beta2);
    bn_pool_kernel<<<blk_h4, T>>>(buf3, bt);

    // ---- pool decode + final linear ----
    pool_decode_kernel<<<(GG * HH + T - 1) / T, T>>>();
    {
        dim3 grid(OUTC / BN, (GG + BM - 1) / BM);
        gemm_f16s<<<grid, 256>>>(pooled, Wf, bf, out, GG, OUTC, HH);
    }
}

// round 10
// speedup vs baseline: 2.5220x; 1.0196x over previous
#include <cuda_runtime.h>
#include <cuda_fp16.h>
#include <math.h>

#define NN   100000
#define EE   300000
#define DINF 128
#define HH   512
#define GG   4096
#define OUTC 256
#define SLOPE 0.01f
#define EPS   1e-5f

// -------- scratch (device globals: allocation-free, 256B aligned) --------
__device__ __align__(256) int      g_cnt[NN];
__device__ __align__(256) int      g_cur[NN];
__device__ __align__(256) int      g_off[NN + 1];
__device__ __align__(256) int      g_srow[EE];
__device__ __align__(256) float    g_snorm[EE];
__device__ __align__(256) float    g_dinv[NN];
__device__ __align__(256) float    g_selfc[NN];
__device__ __align__(256) float    g_buf1[(size_t)NN * HH];   // P1
__device__ __align__(256) float    g_buf2[(size_t)NN * HH];   // Xa then Za
__device__ __align__(256) float    g_buf3[(size_t)NN * HH];   // P2
__device__ __align__(256) unsigned g_keys[(size_t)GG * HH];
__device__ __align__(256) float    g_pooled[(size_t)GG * HH];
__device__ __align__(256) float    g_stats[4 * HH];
__device__ __align__(256) float    g_bna[HH];
__device__ __align__(256) float    g_bnc[HH];

// -------- init (per-call: graph replays must reset all mutable state) --------
__global__ void init_kernel() {
    int i = blockIdx.x * blockDim.x + threadIdx.x;
    if (i < NN) { g_cnt[i] = 0; g_cur[i] = 0; }
    if (i < GG * HH) g_keys[i] = 0u;
    if (i < 4 * HH) g_stats[i] = 0.0f;
}

__global__ void count_deg_kernel(const int* __restrict__ ecol) {
    int e = blockIdx.x * blockDim.x + threadIdx.x;
    if (e < EE) atomicAdd(&g_cnt[ecol[e]], 1);
}

// single-block exclusive scan over g_cnt -> g_off
__global__ void scan_kernel() {
    __shared__ int sh[1024];
    __shared__ int carry;
    int t = threadIdx.x;
    if (t == 0) carry = 0;
    __syncthreads();
    for (int base = 0; base < NN; base += 1024) {
        int i = base + t;
        int v = (i < NN) ? g_cnt[i] : 0;
        sh[t] = v;
        __syncthreads();
        for (int s = 1; s < 1024; s <<= 1) {
            int add = (t >= s) ? sh[t - s] : 0;
            __syncthreads();
            sh[t] += add;
            __syncthreads();
        }
        if (i < NN) g_off[i] = carry + sh[t] - v;   // exclusive
        int total = sh[1023];
        __syncthreads();
        if (t == 0) carry += total;
        __syncthreads();
    }
    if (t == 0) g_off[NN] = carry;
}

__global__ void dinv_kernel() {
    int i = blockIdx.x * blockDim.x + threadIdx.x;
    if (i < NN) {
        float d = (float)g_cnt[i] + 2.0f;
        float di = rsqrtf(d);
        g_dinv[i] = di;
        g_selfc[i] = 2.0f * di * di;
    }
}

// fill CSR: edges sorted by destination col, norm precomputed
__global__ void edge_fill_kernel(const int* __restrict__ erow,
                                 const int* __restrict__ ecol) {
    int e = blockIdx.x * blockDim.x + threadIdx.x;
    if (e >= EE) return;
    int r = erow[e];
    int c = ecol[e];
    int pos = g_off[c] + atomicAdd(&g_cur[c], 1);
    g_srow[pos] = r;
    g_snorm[pos] = g_dinv[r] * g_dinv[c];
}

// -------- layer-1 gather: xa[n] = selfc[n]*x[n] + sum norm*x[src] (W=128) --------
__global__ void gather_x_kernel(const float* __restrict__ x, float* __restrict__ xa) {
    long long gid = (long long)blockIdx.x * blockDim.x + threadIdx.x;
    int node = (int)(gid >> 5);
    int f = (int)(gid & 31) * 4;
    if (node >= NN) return;
    int s = g_off[node], epd = g_off[node + 1];
    float sc = g_selfc[node];
    float4 v = *reinterpret_cast<const float4*>(x + (long long)node * DINF + f);
    float4 acc = make_float4(v.x * sc, v.y * sc, v.z * sc, v.w * sc);
    for (int e = s; e < epd; e++) {
        int r = g_srow[e];
        float nm = g_snorm[e];
        float4 u = *reinterpret_cast<const float4*>(x + (long long)r * DINF + f);
        acc.x = fmaf(nm, u.x, acc.x);
        acc.y = fmaf(nm, u.y, acc.y);
        acc.z = fmaf(nm, u.z, acc.z);
        acc.w = fmaf(nm, u.w, acc.w);
    }
    *reinterpret_cast<float4*>(xa + (long long)node * DINF + f) = acc;
}

// -------- layer-2 gather on Z = lrelu(bn1(P1)), BN recomputed inline (W=512) ----
__device__ __forceinline__ float4 zval(const float* __restrict__ P1, int row, int f) {
    float4 v = *reinterpret_cast<const float4*>(P1 + (long long)row * HH + f);
    float4 a = *reinterpret_cast<const float4*>(g_bna + f);
    float4 c = *reinterpret_cast<const float4*>(g_bnc + f);
    float4 z;
    z.x = fmaf(a.x, v.x, c.x); z.y = fmaf(a.y, v.y, c.y);
    z.z = fmaf(a.z, v.z, c.z); z.w = fmaf(a.w, v.w, c.w);
    z.x = z.x > 0.f ? z.x : SLOPE * z.x;
    z.y = z.y > 0.f ? z.y : SLOPE * z.y;
    z.z = z.z > 0.f ? z.z : SLOPE * z.z;
    z.w = z.w > 0.f ? z.w : SLOPE * z.w;
    return z;
}

__global__ void gather_z_kernel(const float* __restrict__ P1, float* __restrict__ za) {
    long long gid = (long long)blockIdx.x * blockDim.x + threadIdx.x;
    int node = (int)(gid >> 7);
    int f = (int)(gid & 127) * 4;
    if (node >= NN) return;
    int s = g_off[node], epd = g_off[node + 1];
    float sc = g_selfc[node];
    float4 z = zval(P1, node, f);
    float4 acc = make_float4(z.x * sc, z.y * sc, z.z * sc, z.w * sc);
    for (int e = s; e < epd; e++) {
        int r = g_srow[e];
        float nm = g_snorm[e];
        float4 u = zval(P1, r, f);
        acc.x = fmaf(nm, u.x, acc.x);
        acc.y = fmaf(nm, u.y, acc.y);
        acc.z = fmaf(nm, u.z, acc.z);
        acc.w = fmaf(nm, u.w, acc.w);
    }
    *reinterpret_cast<float4*>(za + (long long)node * HH + f) = acc;
}

// -------- FP16 2-split (3-product) tensor-core GEMM, ldmatrix operands --------
#define BM 128
#define BN 128
#define BKT 32
#define ASTR 56
#define BSTR 136

__device__ __forceinline__ void f16_split(float x, __half &hi, __half &lo) {
    __half h = __float2half_rn(x);
    hi = h;
    lo = __float2half_rn(x - __half2float(h));
}

__device__ __forceinline__ void mma_f16(float c[4], const unsigned a[4],
                                        unsigned b0, unsigned b1) {
    asm("mma.sync.aligned.m16n8k16.row.col.f32.f16.f16.f32 "
        "{%0,%1,%2,%3},{%4,%5,%6,%7},{%8,%9},{%0,%1,%2,%3};"
        : "+f"(c[0]), "+f"(c[1]), "+f"(c[2]), "+f"(c[3])
        : "r"(a[0]), "r"(a[1]), "r"(a[2]), "r"(a[3]), "r"(b0), "r"(b1));
}

__device__ __forceinline__ void ldsm_x4(unsigned r[4], unsigned saddr) {
    asm volatile("ldmatrix.sync.aligned.m8n8.x4.shared.b16 {%0,%1,%2,%3}, [%4];"
                 : "=r"(r[0]), "=r"(r[1]), "=r"(r[2]), "=r"(r[3]) : "r"(saddr));
}

__device__ __forceinline__ void ldsm_x2t(unsigned &r0, unsigned &r1, unsigned saddr) {
    asm volatile("ldmatrix.sync.aligned.m8n8.x2.trans.shared.b16 {%0,%1}, [%2];"
                 : "=r"(r0), "=r"(r1) : "r"(saddr));
}

__global__ __launch_bounds__(256)
void gemm_f16s(const float* __restrict__ A, const float* __restrict__ B,
               const float* __restrict__ bias, float* __restrict__ C,
               int M, int N, int K) {
    __shared__ __align__(16) __half Ah[BM][ASTR], Al[BM][ASTR];
    __shared__ __align__(16) __half Bh[BKT][BSTR], Bl[BKT][BSTR];

    int tid  = threadIdx.x;
    int lane = tid & 31;
    int warp = tid >> 5;
    int warpM = warp & 3;
    int warpN = warp >> 2;
    int bm = blockIdx.y * BM;
    int bn = blockIdx.x * BN;

    float acc[2][8][4];
#pragma unroll
    for (int i = 0; i < 2; i++)
#pragma unroll
        for (int j = 0; j < 8; j++)
#pragma unroll
            for (int r = 0; r < 4; r++) acc[i][j][r] = 0.0f;

    int arow = tid >> 1;
    int ak0  = (tid & 1) * 16;
    int bkr  = tid >> 3;
    int bc0  = (tid & 7) * 16;

    unsigned a_base_h = (unsigned)__cvta_generic_to_shared(&Ah[0][0]);
    unsigned a_base_l = (unsigned)__cvta_generic_to_shared(&Al[0][0]);
    unsigned b_base_h = (unsigned)__cvta_generic_to_shared(&Bh[0][0]);
    unsigned b_base_l = (unsigned)__cvta_generic_to_shared(&Bl[0][0]);

    for (int k0 = 0; k0 < K; k0 += BKT) {
        {
            bool inM = (bm + arow < M);
            const float* ap = A + (long long)(bm + arow) * K + k0 + ak0;
#pragma unroll
            for (int q = 0; q < 4; q++) {
                float4 av = inM ? *reinterpret_cast<const float4*>(ap + q * 4)
                                : make_float4(0.f, 0.f, 0.f, 0.f);
                float vv[4] = {av.x, av.y, av.z, av.w};
#pragma unroll
                for (int j = 0; j < 4; j++) {
                    int kc = ak0 + q * 4 + j;
                    __half h, l;
                    f16_split(vv[j], h, l);
                    Ah[arow][kc] = h;
                    Al[arow][kc] = l;
                }
            }
        }
        {
            const float* bp = B + (long long)(k0 + bkr) * N + bn + bc0;
#pragma unroll
            for (int q = 0; q < 4; q++) {
                float4 bv = *reinterpret_cast<const float4*>(bp + q * 4);
                float vv[4] = {bv.x, bv.y, bv.z, bv.w};
#pragma unroll
                for (int j = 0; j < 4; j++) {
                    __half h, l;
                    f16_split(vv[j], h, l);
                    Bh[bkr][bc0 + q * 4 + j] = h;
                    Bl[bkr][bc0 + q * 4 + j] = l;
                }
            }
        }
        __syncthreads();

#pragma unroll
        for (int kk = 0; kk < BKT; kk += 16) {
            unsigned ahi[2][4], alo[2][4];
            int lr = lane & 15;
            int acol = kk + ((lane >> 4) << 3);
#pragma unroll
            for (int mt = 0; mt < 2; mt++) {
                int r = warpM * 32 + mt * 16 + lr;
                unsigned off = (unsigned)(r * ASTR + acol) * 2u;
                ldsm_x4(ahi[mt], a_base_h + off);
                ldsm_x4(alo[mt], a_base_l + off);
            }
            int kr = kk + (lane & 15);
#pragma unroll
            for (int nt = 0; nt < 8; nt++) {
                int n0 = warpN * 64 + nt * 8;
                unsigned boff = (unsigned)(kr * BSTR + n0) * 2u;
                unsigned bh0, bh1, bl0, bl1;
                ldsm_x2t(bh0, bh1, b_base_h + boff);
                ldsm_x2t(bl0, bl1, b_base_l + boff);
#pragma unroll
                for (int mt = 0; mt < 2; mt++) {
                    mma_f16(acc[mt][nt], ahi[mt], bh0, bh1);
                    mma_f16(acc[mt][nt], ahi[mt], bl0, bl1);
                    mma_f16(acc[mt][nt], alo[mt], bh0, bh1);
                }
            }
        }
        __syncthreads();
    }

#pragma unroll
    for (int mt = 0; mt < 2; mt++) {
#pragma unroll
        for (int half = 0; half < 2; half++) {
            int row = bm + warpM * 32 + mt * 16 + (lane >> 2) + half * 8;
            if (row >= M) continue;
#pragma unroll
            for (int nt = 0; nt < 8; nt++) {
                int col = bn + warpN * 64 + nt * 8 + (lane & 3) * 2;
                float v0 = acc[mt][nt][half * 2 + 0];
                float v1 = acc[mt][nt][half * 2 + 1];
                if (bias) { v0 += bias[col]; v1 += bias[col + 1]; }
                *reinterpret_cast<float2*>(C + (long long)row * N + col) =
                    make_float2(v0, v1);
            }
        }
    }
}

// -------- batchnorm stats/coefs --------
__global__ void bn_stats_kernel(const float* __restrict__ X, float* __restrict__ sum,
                                float* __restrict__ sumsq) {
    int f = threadIdx.x;
    float s = 0.f, s2 = 0.f;
    for (int r = blockIdx.x; r < NN; r += gridDim.x) {
        float v = X[(long long)r * HH + f];
        s += v;
        s2 += v * v;
    }
    atomicAdd(&sum[f], s);
    atomicAdd(&sumsq[f], s2);
}

__global__ void bn_coef_kernel(const float* __restrict__ sum, const float* __restrict__ sumsq,
                               const float* __restrict__ g, const float* __restrict__ beta) {
    int f = threadIdx.x;
    float invN = 1.0f / (float)NN;
    float mu = sum[f] * invN;
    float var = fmaxf(sumsq[f] * invN - mu * mu, 0.0f);
    float s = g[f] * rsqrtf(var + EPS);
    g_bna[f] = s;
    g_bnc[f] = beta[f] - s * mu;
}

// -------- fused BN-apply + LeakyReLU + segment-max pool (layer 2) --------
__global__ void bn_pool_kernel(const float* __restrict__ X, const int* __restrict__ batch) {
    long long i4 = (long long)blockIdx.x * blockDim.x + threadIdx.x;
    long long base = i4 * 4;
    if (base >= (long long)NN * HH) return;
    int node = (int)(base >> 9);
    int f = (int)(base & 511);
    int grp = batch[node];
    float4 v = *reinterpret_cast<const float4*>(X + base);
    float4 a = *reinterpret_cast<const float4*>(g_bna + f);
    float4 c = *reinterpret_cast<const float4*>(g_bnc + f);
    float o[4];
    o[0] = fmaf(a.x, v.x, c.x); o[1] = fmaf(a.y, v.y, c.y);
    o[2] = fmaf(a.z, v.z, c.z); o[3] = fmaf(a.w, v.w, c.w);
    unsigned* dst = &g_keys[(long long)grp * HH + f];
#pragma unroll
    for (int j = 0; j < 4; j++) {
        float ov = o[j] > 0.f ? o[j] : SLOPE * o[j];
        unsigned u = __float_as_uint(ov);
        u = (u & 0x80000000u) ? ~u : (u | 0x80000000u);
        atomicMax(&dst[j], u);
    }
}

__global__ void pool_decode_kernel() {
    long long i = (long long)blockIdx.x * blockDim.x + threadIdx.x;
    if (i >= (long long)GG * HH) return;
    unsigned k = g_keys[i];
    float v;
    if (k == 0u) {
        v = 0.0f;
    } else {
        unsigned u = (k & 0x80000000u) ? (k & 0x7fffffffu) : ~k;
        v = __uint_as_float(u);
    }
    g_pooled[i] = v;
}

// -------- host launch --------
extern "C" void kernel_launch(void* const* d_in, const int* in_sizes, int n_in,
                              void* d_out, int out_size) {
    const float* x      = (const float*)d_in[0];
    const int*   ei     = (const int*)d_in[1];
    const int*   bt     = (const int*)d_in[2];
    const float* W1     = (const float*)d_in[3];
    const float* b1     = (const float*)d_in[4];
    const float* g1     = (const float*)d_in[5];
    const float* beta1  = (const float*)d_in[6];
    const float* W2     = (const float*)d_in[7];
    const float* b2     = (const float*)d_in[8];
    const float* g2     = (const float*)d_in[9];
    const float* beta2  = (const float*)d_in[10];
    const float* Wf     = (const float*)d_in[11];
    const float* bf     = (const float*)d_in[12];
    float* out = (float*)d_out;

    const int* erow = ei;
    const int* ecol = ei + EE;

    float *buf1, *buf2, *buf3, *pooled, *stats;
    cudaGetSymbolAddress((void**)&buf1, g_buf1);
    cudaGetSymbolAddress((void**)&buf2, g_buf2);
    cudaGetSymbolAddress((void**)&buf3, g_buf3);
    cudaGetSymbolAddress((void**)&pooled, g_pooled);
    cudaGetSymbolAddress((void**)&stats, g_stats);

    const int T = 256;
    init_kernel<<<(GG * HH + T - 1) / T, T>>>();
    count_deg_kernel<<<(EE + T - 1) / T, T>>>(ecol);
    scan_kernel<<<1, 1024>>>();
    dinv_kernel<<<(NN + T - 1) / T, T>>>();
    edge_fill_kernel<<<(EE + T - 1) / T, T>>>(erow, ecol);

    long long elemsH = (long long)NN * HH;
    int blk_h4 = (int)((elemsH / 4 + T - 1) / T);
    int blk_gx = (int)(((long long)NN * 32 + T - 1) / T);
    int blk_gz = (int)(((long long)NN * 128 + T - 1) / T);

    // ---- layer 1: gather-aggregate X (N x 128), then GEMM ----
    gather_x_kernel<<<blk_gx, T>>>(x, buf2);
    {
        dim3 grid(HH / BN, (NN + BM - 1) / BM);
        gemm_f16s<<<grid, 256>>>(buf2, W1, b1, buf1, NN, HH, DINF);   // P1
    }
    bn_stats_kernel<<<1024, HH>>>(buf1, stats + 0, stats + HH);
    bn_coef_kernel<<<1, HH>>>(stats + 0, stats + HH, g1, beta1);

    // ---- layer 2: gather-aggregate Z = lrelu(bn1(P1)) (BN inline), then GEMM ----
    gather_z_kernel<<<blk_gz, T>>>(buf1, buf2);
    {
        dim3 grid(HH / BN, (NN + BM - 1) / BM);
        gemm_f16s<<<grid, 256>>>(buf2, W2, b2, buf3, NN, HH, HH);     // P2
    }
    bn_stats_kernel<<<1024, HH>>>(buf3, stats + 2 * HH, stats + 3 * HH);
    bn_coef_kernel<<<1, HH>>>(stats + 2 * HH, stats + 3 * HH, g2, beta2);
    bn_pool_kernel<<<blk_h4, T>>>(buf3, bt);

    // ---- pool decode + final linear ----
    pool_decode_kernel<<<(GG * HH + T - 1) / T, T>>>();
    {
        dim3 grid(OUTC / BN, (GG + BM - 1) / BM);
        gemm_f16s<<<grid, 256>>>(pooled, Wf, bf, out, GG, OUTC, HH);
    }
}

// round 12
// speedup vs baseline: 2.9854x; 1.1838x over previous
#include <cuda_runtime.h>
#include <cuda_fp16.h>
#include <math.h>

#define NN   100000
#define EE   300000
#define DINF 128
#define HH   512
#define GG   4096
#define OUTC 256
#define SLOPE 0.01f
#define EPS   1e-5f

// -------- scratch (device globals: allocation-free, 256B aligned) --------
__device__ __align__(256) int      g_cnt[NN];
__device__ __align__(256) int      g_cur[NN];
__device__ __align__(256) int      g_off[NN + 1];
__device__ __align__(256) int      g_srow[EE];
__device__ __align__(256) float    g_snorm[EE];
__device__ __align__(256) float    g_dinv[NN];
__device__ __align__(256) float    g_selfc[NN];
__device__ __align__(256) int      g_gstart[GG];
__device__ __align__(256) int      g_gend[GG];
__device__ __align__(256) float    g_buf1[(size_t)NN * HH];   // P1
__device__ __align__(256) float    g_buf2[(size_t)NN * HH];   // Xa then Za
__device__ __align__(256) float    g_buf3[(size_t)NN * HH];   // P2
__device__ __align__(256) float    g_pooled[(size_t)GG * HH];
__device__ __align__(256) float    g_stats[4 * HH];
__device__ __align__(256) float    g_bna[HH];
__device__ __align__(256) float    g_bnc[HH];

// -------- init (per-call: graph replays must reset all mutable state) --------
__global__ void init_kernel() {
    int i = blockIdx.x * blockDim.x + threadIdx.x;
    if (i < NN) { g_cnt[i] = 0; g_cur[i] = 0; }
    if (i < GG) { g_gstart[i] = 0; g_gend[i] = 0; }
    if (i < 4 * HH) g_stats[i] = 0.0f;
}

__global__ void count_deg_kernel(const int* __restrict__ ecol) {
    int e = blockIdx.x * blockDim.x + threadIdx.x;
    if (e < EE) atomicAdd(&g_cnt[ecol[e]], 1);
}

// single-block exclusive scan over g_cnt -> g_off
__global__ void scan_kernel() {
    __shared__ int sh[1024];
    __shared__ int carry;
    int t = threadIdx.x;
    if (t == 0) carry = 0;
    __syncthreads();
    for (int base = 0; base < NN; base += 1024) {
        int i = base + t;
        int v = (i < NN) ? g_cnt[i] : 0;
        sh[t] = v;
        __syncthreads();
        for (int s = 1; s < 1024; s <<= 1) {
            int add = (t >= s) ? sh[t - s] : 0;
            __syncthreads();
            sh[t] += add;
            __syncthreads();
        }
        if (i < NN) g_off[i] = carry + sh[t] - v;   // exclusive
        int total = sh[1023];
        __syncthreads();
        if (t == 0) carry += total;
        __syncthreads();
    }
    if (t == 0) g_off[NN] = carry;
}

__global__ void dinv_kernel() {
    int i = blockIdx.x * blockDim.x + threadIdx.x;
    if (i < NN) {
        float d = (float)g_cnt[i] + 2.0f;
        float di = rsqrtf(d);
        g_dinv[i] = di;
        g_selfc[i] = 2.0f * di * di;
    }
}

__global__ void edge_fill_kernel(const int* __restrict__ erow,
                                 const int* __restrict__ ecol) {
    int e = blockIdx.x * blockDim.x + threadIdx.x;
    if (e >= EE) return;
    int r = erow[e];
    int c = ecol[e];
    int pos = g_off[c] + atomicAdd(&g_cur[c], 1);
    g_srow[pos] = r;
    g_snorm[pos] = g_dinv[r] * g_dinv[c];
}

// batch is sorted: record [start,end) row range per graph
__global__ void seg_bounds_kernel(const int* __restrict__ bt) {
    int i = blockIdx.x * blockDim.x + threadIdx.x;
    if (i >= NN) return;
    int b = bt[i];
    if (i == 0 || bt[i - 1] != b) g_gstart[b] = i;
    if (i == NN - 1 || bt[i + 1] != b) g_gend[b] = i + 1;
}

// -------- layer-1 gather (W=128) --------
__global__ void gather_x_kernel(const float* __restrict__ x, float* __restrict__ xa) {
    long long gid = (long long)blockIdx.x * blockDim.x + threadIdx.x;
    int node = (int)(gid >> 5);
    int f = (int)(gid & 31) * 4;
    if (node >= NN) return;
    int s = g_off[node], epd = g_off[node + 1];
    float sc = g_selfc[node];
    float4 v = *reinterpret_cast<const float4*>(x + (long long)node * DINF + f);
    float4 acc = make_float4(v.x * sc, v.y * sc, v.z * sc, v.w * sc);
    for (int e = s; e < epd; e++) {
        int r = g_srow[e];
        float nm = g_snorm[e];
        float4 u = *reinterpret_cast<const float4*>(x + (long long)r * DINF + f);
        acc.x = fmaf(nm, u.x, acc.x);
        acc.y = fmaf(nm, u.y, acc.y);
        acc.z = fmaf(nm, u.z, acc.z);
        acc.w = fmaf(nm, u.w, acc.w);
    }
    *reinterpret_cast<float4*>(xa + (long long)node * DINF + f) = acc;
}

// -------- layer-2 gather on Z = lrelu(bn1(P1)), BN inline (W=512) --------
__device__ __forceinline__ float4 zval(const float* __restrict__ P1, int row, int f) {
    float4 v = *reinterpret_cast<const float4*>(P1 + (long long)row * HH + f);
    float4 a = *reinterpret_cast<const float4*>(g_bna + f);
    float4 c = *reinterpret_cast<const float4*>(g_bnc + f);
    float4 z;
    z.x = fmaf(a.x, v.x, c.x); z.y = fmaf(a.y, v.y, c.y);
    z.z = fmaf(a.z, v.z, c.z); z.w = fmaf(a.w, v.w, c.w);
    z.x = z.x > 0.f ? z.x : SLOPE * z.x;
    z.y = z.y > 0.f ? z.y : SLOPE * z.y;
    z.z = z.z > 0.f ? z.z : SLOPE * z.z;
    z.w = z.w > 0.f ? z.w : SLOPE * z.w;
    return z;
}

__global__ void gather_z_kernel(const float* __restrict__ P1, float* __restrict__ za) {
    long long gid = (long long)blockIdx.x * blockDim.x + threadIdx.x;
    int node = (int)(gid >> 7);
    int f = (int)(gid & 127) * 4;
    if (node >= NN) return;
    int s = g_off[node], epd = g_off[node + 1];
    float sc = g_selfc[node];
    float4 z = zval(P1, node, f);
    float4 acc = make_float4(z.x * sc, z.y * sc, z.z * sc, z.w * sc);
    for (int e = s; e < epd; e++) {
        int r = g_srow[e];
        float nm = g_snorm[e];
        float4 u = zval(P1, r, f);
        acc.x = fmaf(nm, u.x, acc.x);
        acc.y = fmaf(nm, u.y, acc.y);
        acc.z = fmaf(nm, u.z, acc.z);
        acc.w = fmaf(nm, u.w, acc.w);
    }
    *reinterpret_cast<float4*>(za + (long long)node * HH + f) = acc;
}

// -------- FP16 2-split GEMM + optional fused column stats (sum, sumsq) --------
#define BM 128
#define BN 128
#define BKT 32
#define ASTR 56
#define BSTR 136

__device__ __forceinline__ void f16_split(float x, __half &hi, __half &lo) {
    __half h = __float2half_rn(x);
    hi = h;
    lo = __float2half_rn(x - __half2float(h));
}

__device__ __forceinline__ void mma_f16(float c[4], const unsigned a[4],
                                        unsigned b0, unsigned b1) {
    asm("mma.sync.aligned.m16n8k16.row.col.f32.f16.f16.f32 "
        "{%0,%1,%2,%3},{%4,%5,%6,%7},{%8,%9},{%0,%1,%2,%3};"
        : "+f"(c[0]), "+f"(c[1]), "+f"(c[2]), "+f"(c[3])
        : "r"(a[0]), "r"(a[1]), "r"(a[2]), "r"(a[3]), "r"(b0), "r"(b1));
}

__device__ __forceinline__ void ldsm_x4(unsigned r[4], unsigned saddr) {
    asm volatile("ldmatrix.sync.aligned.m8n8.x4.shared.b16 {%0,%1,%2,%3}, [%4];"
                 : "=r"(r[0]), "=r"(r[1]), "=r"(r[2]), "=r"(r[3]) : "r"(saddr));
}

__device__ __forceinline__ void ldsm_x2t(unsigned &r0, unsigned &r1, unsigned saddr) {
    asm volatile("ldmatrix.sync.aligned.m8n8.x2.trans.shared.b16 {%0,%1}, [%2];"
                 : "=r"(r0), "=r"(r1) : "r"(saddr));
}

__global__ __launch_bounds__(256)
void gemm_f16s(const float* __restrict__ A, const float* __restrict__ B,
               const float* __restrict__ bias, float* __restrict__ C,
               float* __restrict__ statSum, float* __restrict__ statSq,
               int M, int N, int K) {
    __shared__ __align__(16) __half Ah[BM][ASTR], Al[BM][ASTR];
    __shared__ __align__(16) __half Bh[BKT][BSTR], Bl[BKT][BSTR];

    int tid  = threadIdx.x;
    int lane = tid & 31;
    int warp = tid >> 5;
    int warpM = warp & 3;
    int warpN = warp >> 2;
    int bm = blockIdx.y * BM;
    int bn = blockIdx.x * BN;

    float acc[2][8][4];
#pragma unroll
    for (int i = 0; i < 2; i++)
#pragma unroll
        for (int j = 0; j < 8; j++)
#pragma unroll
            for (int r = 0; r < 4; r++) acc[i][j][r] = 0.0f;

    int arow = tid >> 1;
    int ak0  = (tid & 1) * 16;
    int bkr  = tid >> 3;
    int bc0  = (tid & 7) * 16;

    unsigned a_base_h = (unsigned)__cvta_generic_to_shared(&Ah[0][0]);
    unsigned a_base_l = (unsigned)__cvta_generic_to_shared(&Al[0][0]);
    unsigned b_base_h = (unsigned)__cvta_generic_to_shared(&Bh[0][0]);
    unsigned b_base_l = (unsigned)__cvta_generic_to_shared(&Bl[0][0]);

    for (int k0 = 0; k0 < K; k0 += BKT) {
        {
            bool inM = (bm + arow < M);
            const float* ap = A + (long long)(bm + arow) * K + k0 + ak0;
#pragma unroll
            for (int q = 0; q < 4; q++) {
                float4 av = inM ? *reinterpret_cast<const float4*>(ap + q * 4)
                                : make_float4(0.f, 0.f, 0.f, 0.f);
                float vv[4] = {av.x, av.y, av.z, av.w};
#pragma unroll
                for (int j = 0; j < 4; j++) {
                    int kc = ak0 + q * 4 + j;
                    __half h, l;
                    f16_split(vv[j], h, l);
                    Ah[arow][kc] = h;
                    Al[arow][kc] = l;
                }
            }
        }
        {
            const float* bp = B + (long long)(k0 + bkr) * N + bn + bc0;
#pragma unroll
            for (int q = 0; q < 4; q++) {
                float4 bv = *reinterpret_cast<const float4*>(bp + q * 4);
                float vv[4] = {bv.x, bv.y, bv.z, bv.w};
#pragma unroll
                for (int j = 0; j < 4; j++) {
                    __half h, l;
                    f16_split(vv[j], h, l);
                    Bh[bkr][bc0 + q * 4 + j] = h;
                    Bl[bkr][bc0 + q * 4 + j] = l;
                }
            }
        }
        __syncthreads();

#pragma unroll
        for (int kk = 0; kk < BKT; kk += 16) {
            unsigned ahi[2][4], alo[2][4];
            int lr = lane & 15;
            int acol = kk + ((lane >> 4) << 3);
#pragma unroll
            for (int mt = 0; mt < 2; mt++) {
                int r = warpM * 32 + mt * 16 + lr;
                unsigned off = (unsigned)(r * ASTR + acol) * 2u;
                ldsm_x4(ahi[mt], a_base_h + off);
                ldsm_x4(alo[mt], a_base_l + off);
            }
            int kr = kk + (lane & 15);
#pragma unroll
            for (int nt = 0; nt < 8; nt++) {
                int n0 = warpN * 64 + nt * 8;
                unsigned boff = (unsigned)(kr * BSTR + n0) * 2u;
                unsigned bh0, bh1, bl0, bl1;
                ldsm_x2t(bh0, bh1, b_base_h + boff);
                ldsm_x2t(bl0, bl1, b_base_l + boff);
#pragma unroll
                for (int mt = 0; mt < 2; mt++) {
                    mma_f16(acc[mt][nt], ahi[mt], bh0, bh1);
                    mma_f16(acc[mt][nt], ahi[mt], bl0, bl1);
                    mma_f16(acc[mt][nt], alo[mt], bh0, bh1);
                }
            }
        }
        __syncthreads();
    }

    // ---- epilogue: write C and accumulate column stats ----
    float cs[16], cq[16];
#pragma unroll
    for (int i = 0; i < 16; i++) { cs[i] = 0.f; cq[i] = 0.f; }

#pragma unroll
    for (int mt = 0; mt < 2; mt++) {
#pragma unroll
        for (int half = 0; half < 2; half++) {
            int row = bm + warpM * 32 + mt * 16 + (lane >> 2) + half * 8;
            if (row >= M) continue;
#pragma unroll
            for (int nt = 0; nt < 8; nt++) {
                int col = bn + warpN * 64 + nt * 8 + (lane & 3) * 2;
                float v0 = acc[mt][nt][half * 2 + 0];
                float v1 = acc[mt][nt][half * 2 + 1];
                if (bias) { v0 += bias[col]; v1 += bias[col + 1]; }
                *reinterpret_cast<float2*>(C + (long long)row * N + col) =
                    make_float2(v0, v1);
                if (statSum) {
                    cs[nt * 2]     += v0; cq[nt * 2]     += v0 * v0;
                    cs[nt * 2 + 1] += v1; cq[nt * 2 + 1] += v1 * v1;
                }
            }
        }
    }
    if (statSum) {
#pragma unroll
        for (int i = 0; i < 16; i++) {
#pragma unroll
            for (int s = 4; s < 32; s <<= 1) {
                cs[i] += __shfl_xor_sync(0xffffffffu, cs[i], s);
                cq[i] += __shfl_xor_sync(0xffffffffu, cq[i], s);
            }
        }
        if (lane < 4) {
#pragma unroll
            for (int nt = 0; nt < 8; nt++) {
                int col = bn + warpN * 64 + nt * 8 + lane * 2;
                atomicAdd(&statSum[col],     cs[nt * 2]);
                atomicAdd(&statSq[col],      cq[nt * 2]);
                atomicAdd(&statSum[col + 1], cs[nt * 2 + 1]);
                atomicAdd(&statSq[col + 1],  cq[nt * 2 + 1]);
            }
        }
    }
}

// -------- bn coefs --------
__global__ void bn_coef_kernel(const float* __restrict__ sum, const float* __restrict__ sumsq,
                               const float* __restrict__ g, const float* __restrict__ beta) {
    int f = threadIdx.x;
    float invN = 1.0f / (float)NN;
    float mu = sum[f] * invN;
    float var = fmaxf(sumsq[f] * invN - mu * mu, 0.0f);
    float s = g[f] * rsqrtf(var + EPS);
    g_bna[f] = s;
    g_bnc[f] = beta[f] - s * mu;
}

// -------- segmented max pool over sorted batch, bn2+lrelu fused --------
__global__ __launch_bounds__(128)
void pool_seg_kernel(const float* __restrict__ P2) {
    int g = blockIdx.x;
    int f = threadIdx.x * 4;
    int s = g_gstart[g], e = g_gend[g];
    float4 a = *reinterpret_cast<const float4*>(g_bna + f);
    float4 c = *reinterpret_cast<const float4*>(g_bnc + f);
    float m0 = -INFINITY, m1 = -INFINITY, m2 = -INFINITY, m3 = -INFINITY;
    for (int r = s; r < e; r++) {
        float4 v = *reinterpret_cast<const float4*>(P2 + (long long)r * HH + f);
        float z0 = fmaf(a.x, v.x, c.x);
        float z1 = fmaf(a.y, v.y, c.y);
        float z2 = fmaf(a.z, v.z, c.z);
        float z3 = fmaf(a.w, v.w, c.w);
        z0 = z0 > 0.f ? z0 : SLOPE * z0;
        z1 = z1 > 0.f ? z1 : SLOPE * z1;
        z2 = z2 > 0.f ? z2 : SLOPE * z2;
        z3 = z3 > 0.f ? z3 : SLOPE * z3;
        m0 = fmaxf(m0, z0); m1 = fmaxf(m1, z1);
        m2 = fmaxf(m2, z2); m3 = fmaxf(m3, z3);
    }
    float4 o;
    if (e <= s) o = make_float4(0.f, 0.f, 0.f, 0.f);
    else        o = make_float4(m0, m1, m2, m3);
    *reinterpret_cast<float4*>(g_pooled + (long long)g * HH + f) = o;
}

// -------- host launch --------
extern "C" void kernel_launch(void* const* d_in, const int* in_sizes, int n_in,
                              void* d_out, int out_size) {
    const float* x      = (const float*)d_in[0];
    const int*   ei     = (const int*)d_in[1];
    const int*   bt     = (const int*)d_in[2];
    const float* W1     = (const float*)d_in[3];
    const float* b1     = (const float*)d_in[4];
    const float* g1     = (const float*)d_in[5];
    const float* beta1  = (const float*)d_in[6];
    const float* W2     = (const float*)d_in[7];
    const float* b2     = (const float*)d_in[8];
    const float* g2     = (const float*)d_in[9];
    const float* beta2  = (const float*)d_in[10];
    const float* Wf     = (const float*)d_in[11];
    const float* bf     = (const float*)d_in[12];
    float* out = (float*)d_out;

    const int* erow = ei;
    const int* ecol = ei + EE;

    float *buf1, *buf2, *buf3, *pooled, *stats;
    cudaGetSymbolAddress((void**)&buf1, g_buf1);
    cudaGetSymbolAddress((void**)&buf2, g_buf2);
    cudaGetSymbolAddress((void**)&buf3, g_buf3);
    cudaGetSymbolAddress((void**)&pooled, g_pooled);
    cudaGetSymbolAddress((void**)&stats, g_stats);

    const int T = 256;
    init_kernel<<<(NN + T - 1) / T, T>>>();
    count_deg_kernel<<<(EE + T - 1) / T, T>>>(ecol);
    scan_kernel<<<1, 1024>>>();
    dinv_kernel<<<(NN + T - 1) / T, T>>>();
    edge_fill_kernel<<<(EE + T - 1) / T, T>>>(erow, ecol);
    seg_bounds_kernel<<<(NN + T - 1) / T, T>>>(bt);

    int blk_gx = (int)(((long long)NN * 32 + T - 1) / T);
    int blk_gz = (int)(((long long)NN * 128 + T - 1) / T);

    // ---- layer 1: gather X, GEMM (+stats1 fused) ----
    gather_x_kernel<<<blk_gx, T>>>(x, buf2);
    {
        dim3 grid(HH / BN, (NN + BM - 1) / BM);
        gemm_f16s<<<grid, 256>>>(buf2, W1, b1, buf1, stats + 0, stats + HH,
                                 NN, HH, DINF);
    }
    bn_coef_kernel<<<1, HH>>>(stats + 0, stats + HH, g1, beta1);

    // ---- layer 2: gather Z (bn1 inline), GEMM (+stats2 fused) ----
    gather_z_kernel<<<blk_gz, T>>>(buf1, buf2);
    {
        dim3 grid(HH / BN, (NN + BM - 1) / BM);
        gemm_f16s<<<grid, 256>>>(buf2, W2, b2, buf3, stats + 2 * HH, stats + 3 * HH,
                                 NN, HH, HH);
    }
    bn_coef_kernel<<<1, HH>>>(stats + 2 * HH, stats + 3 * HH, g2, beta2);

    // ---- segmented pool (bn2+lrelu fused) + final linear ----
    pool_seg_kernel<<<GG, 128>>>(buf3);
    {
        dim3 grid(OUTC / BN, (GG + BM - 1) / BM);
        gemm_f16s<<<grid, 256>>>(pooled, Wf, bf, out, nullptr, nullptr,
                                 GG, OUTC, HH);
    }
}

// round 13
// speedup vs baseline: 3.0594x; 1.0248x over previous
#include <cuda_runtime.h>
#include <cuda_fp16.h>
#include <math.h>

#define NN   100000
#define EE   300000
#define DINF 128
#define HH   512
#define GG   4096
#define OUTC 256
#define SLOPE 0.01f
#define EPS   1e-5f

// -------- scratch (device globals: allocation-free, 256B aligned) --------
__device__ __align__(256) int      g_cnt[NN];
__device__ __align__(256) int      g_cur[NN];
__device__ __align__(256) int      g_off[NN + 1];
__device__ __align__(256) int      g_srow[EE];
__device__ __align__(256) float    g_snorm[EE];
__device__ __align__(256) float    g_dinv[NN];
__device__ __align__(256) float    g_selfc[NN];
__device__ __align__(256) int      g_gstart[GG];
__device__ __align__(256) int      g_gend[GG];
__device__ __align__(256) float    g_buf1[(size_t)NN * HH];   // P1
__device__ __align__(256) float    g_buf2[(size_t)NN * HH];   // Xa then Za
__device__ __align__(256) float    g_buf3[(size_t)NN * HH];   // P2
__device__ __align__(256) float    g_pooled[(size_t)GG * HH];
__device__ __align__(256) float    g_stats[4 * HH];
__device__ __align__(256) float    g_bna[HH];
__device__ __align__(256) float    g_bnc[HH];

// -------- init --------
__global__ void init_kernel() {
    int i = blockIdx.x * blockDim.x + threadIdx.x;
    if (i < NN) { g_cnt[i] = 0; g_cur[i] = 0; }
    if (i < GG) { g_gstart[i] = 0; g_gend[i] = 0; }
    if (i < 4 * HH) g_stats[i] = 0.0f;
}

__global__ void count_deg_kernel(const int* __restrict__ ecol) {
    int e = blockIdx.x * blockDim.x + threadIdx.x;
    if (e < EE) atomicAdd(&g_cnt[ecol[e]], 1);
}

__global__ void scan_kernel() {
    __shared__ int sh[1024];
    __shared__ int carry;
    int t = threadIdx.x;
    if (t == 0) carry = 0;
    __syncthreads();
    for (int base = 0; base < NN; base += 1024) {
        int i = base + t;
        int v = (i < NN) ? g_cnt[i] : 0;
        sh[t] = v;
        __syncthreads();
        for (int s = 1; s < 1024; s <<= 1) {
            int add = (t >= s) ? sh[t - s] : 0;
            __syncthreads();
            sh[t] += add;
            __syncthreads();
        }
        if (i < NN) g_off[i] = carry + sh[t] - v;
        int total = sh[1023];
        __syncthreads();
        if (t == 0) carry += total;
        __syncthreads();
    }
    if (t == 0) g_off[NN] = carry;
}

__global__ void dinv_kernel() {
    int i = blockIdx.x * blockDim.x + threadIdx.x;
    if (i < NN) {
        float d = (float)g_cnt[i] + 2.0f;
        float di = rsqrtf(d);
        g_dinv[i] = di;
        g_selfc[i] = 2.0f * di * di;
    }
}

__global__ void edge_fill_kernel(const int* __restrict__ erow,
                                 const int* __restrict__ ecol) {
    int e = blockIdx.x * blockDim.x + threadIdx.x;
    if (e >= EE) return;
    int r = erow[e];
    int c = ecol[e];
    int pos = g_off[c] + atomicAdd(&g_cur[c], 1);
    g_srow[pos] = r;
    g_snorm[pos] = g_dinv[r] * g_dinv[c];
}

__global__ void seg_bounds_kernel(const int* __restrict__ bt) {
    int i = blockIdx.x * blockDim.x + threadIdx.x;
    if (i >= NN) return;
    int b = bt[i];
    if (i == 0 || bt[i - 1] != b) g_gstart[b] = i;
    if (i == NN - 1 || bt[i + 1] != b) g_gend[b] = i + 1;
}

// -------- layer-1 gather (W=128) --------
__global__ void gather_x_kernel(const float* __restrict__ x, float* __restrict__ xa) {
    long long gid = (long long)blockIdx.x * blockDim.x + threadIdx.x;
    int node = (int)(gid >> 5);
    int f = (int)(gid & 31) * 4;
    if (node >= NN) return;
    int s = g_off[node], epd = g_off[node + 1];
    float sc = g_selfc[node];
    float4 v = *reinterpret_cast<const float4*>(x + (long long)node * DINF + f);
    float4 acc = make_float4(v.x * sc, v.y * sc, v.z * sc, v.w * sc);
#pragma unroll 4
    for (int e = s; e < epd; e++) {
        int r = g_srow[e];
        float nm = g_snorm[e];
        float4 u = *reinterpret_cast<const float4*>(x + (long long)r * DINF + f);
        acc.x = fmaf(nm, u.x, acc.x);
        acc.y = fmaf(nm, u.y, acc.y);
        acc.z = fmaf(nm, u.z, acc.z);
        acc.w = fmaf(nm, u.w, acc.w);
    }
    *reinterpret_cast<float4*>(xa + (long long)node * DINF + f) = acc;
}

// -------- layer-2 gather on Z = lrelu(bn1(P1)), BN inline (W=512) --------
__device__ __forceinline__ float4 zval(const float* __restrict__ P1, int row, int f) {
    float4 v = *reinterpret_cast<const float4*>(P1 + (long long)row * HH + f);
    float4 a = *reinterpret_cast<const float4*>(g_bna + f);
    float4 c = *reinterpret_cast<const float4*>(g_bnc + f);
    float4 z;
    z.x = fmaf(a.x, v.x, c.x); z.y = fmaf(a.y, v.y, c.y);
    z.z = fmaf(a.z, v.z, c.z); z.w = fmaf(a.w, v.w, c.w);
    z.x = z.x > 0.f ? z.x : SLOPE * z.x;
    z.y = z.y > 0.f ? z.y : SLOPE * z.y;
    z.z = z.z > 0.f ? z.z : SLOPE * z.z;
    z.w = z.w > 0.f ? z.w : SLOPE * z.w;
    return z;
}

__global__ void gather_z_kernel(const float* __restrict__ P1, float* __restrict__ za) {
    long long gid = (long long)blockIdx.x * blockDim.x + threadIdx.x;
    int node = (int)(gid >> 7);
    int f = (int)(gid & 127) * 4;
    if (node >= NN) return;
    int s = g_off[node], epd = g_off[node + 1];
    float sc = g_selfc[node];
    float4 z = zval(P1, node, f);
    float4 acc = make_float4(z.x * sc, z.y * sc, z.z * sc, z.w * sc);
#pragma unroll 4
    for (int e = s; e < epd; e++) {
        int r = g_srow[e];
        float nm = g_snorm[e];
        float4 u = zval(P1, r, f);
        acc.x = fmaf(nm, u.x, acc.x);
        acc.y = fmaf(nm, u.y, acc.y);
        acc.z = fmaf(nm, u.z, acc.z);
        acc.w = fmaf(nm, u.w, acc.w);
    }
    *reinterpret_cast<float4*>(za + (long long)node * HH + f) = acc;
}

// -------- FP16 2-split GEMM, register-prefetch pipelined, fused stats --------
#define BM 128
#define BN 128
#define BKT 32
#define ASTR 56
#define BSTR 136

__device__ __forceinline__ void f16_split(float x, __half &hi, __half &lo) {
    __half h = __float2half_rn(x);
    hi = h;
    lo = __float2half_rn(x - __half2float(h));
}

__device__ __forceinline__ void mma_f16(float c[4], const unsigned a[4],
                                        unsigned b0, unsigned b1) {
    asm("mma.sync.aligned.m16n8k16.row.col.f32.f16.f16.f32 "
        "{%0,%1,%2,%3},{%4,%5,%6,%7},{%8,%9},{%0,%1,%2,%3};"
        : "+f"(c[0]), "+f"(c[1]), "+f"(c[2]), "+f"(c[3])
        : "r"(a[0]), "r"(a[1]), "r"(a[2]), "r"(a[3]), "r"(b0), "r"(b1));
}

__device__ __forceinline__ void ldsm_x4(unsigned r[4], unsigned saddr) {
    asm volatile("ldmatrix.sync.aligned.m8n8.x4.shared.b16 {%0,%1,%2,%3}, [%4];"
                 : "=r"(r[0]), "=r"(r[1]), "=r"(r[2]), "=r"(r[3]) : "r"(saddr));
}

__device__ __forceinline__ void ldsm_x2t(unsigned &r0, unsigned &r1, unsigned saddr) {
    asm volatile("ldmatrix.sync.aligned.m8n8.x2.trans.shared.b16 {%0,%1}, [%2];"
                 : "=r"(r0), "=r"(r1) : "r"(saddr));
}

__global__ __launch_bounds__(256)
void gemm_f16s(const float* __restrict__ A, const float* __restrict__ B,
               const float* __restrict__ bias, float* __restrict__ C,
               float* __restrict__ statSum, float* __restrict__ statSq,
               int M, int N, int K) {
    __shared__ __align__(16) __half Ah[BM][ASTR], Al[BM][ASTR];
    __shared__ __align__(16) __half Bh[BKT][BSTR], Bl[BKT][BSTR];

    int tid  = threadIdx.x;
    int lane = tid & 31;
    int warp = tid >> 5;
    int warpM = warp & 3;
    int warpN = warp >> 2;
    int bm = blockIdx.y * BM;
    int bn = blockIdx.x * BN;

    float acc[2][8][4];
#pragma unroll
    for (int i = 0; i < 2; i++)
#pragma unroll
        for (int j = 0; j < 8; j++)
#pragma unroll
            for (int r = 0; r < 4; r++) acc[i][j][r] = 0.0f;

    int arow = tid >> 1;
    int ak0  = (tid & 1) * 16;
    int bkr  = tid >> 3;
    int bc0  = (tid & 7) * 16;
    bool inM = (bm + arow < M);

    unsigned a_base_h = (unsigned)__cvta_generic_to_shared(&Ah[0][0]);
    unsigned a_base_l = (unsigned)__cvta_generic_to_shared(&Al[0][0]);
    unsigned b_base_h = (unsigned)__cvta_generic_to_shared(&Bh[0][0]);
    unsigned b_base_l = (unsigned)__cvta_generic_to_shared(&Bl[0][0]);

    // register staging for prefetched tile
    float4 ra[4], rb[4];

    // prefetch tile k0=0
    {
        const float* ap = A + (long long)(bm + arow) * K + ak0;
        const float* bp = B + (long long)bkr * N + bn + bc0;
#pragma unroll
        for (int q = 0; q < 4; q++) {
            ra[q] = inM ? *reinterpret_cast<const float4*>(ap + q * 4)
                        : make_float4(0.f, 0.f, 0.f, 0.f);
            rb[q] = *reinterpret_cast<const float4*>(bp + q * 4);
        }
    }

    for (int k0 = 0; k0 < K; k0 += BKT) {
        // ---- convert + store staged registers to smem ----
#pragma unroll
        for (int q = 0; q < 4; q++) {
            float av[4] = {ra[q].x, ra[q].y, ra[q].z, ra[q].w};
            float bv[4] = {rb[q].x, rb[q].y, rb[q].z, rb[q].w};
#pragma unroll
            for (int j = 0; j < 4; j++) {
                int kc = ak0 + q * 4 + j;
                __half h, l;
                f16_split(av[j], h, l);
                Ah[arow][kc] = h;
                Al[arow][kc] = l;
                f16_split(bv[j], h, l);
                Bh[bkr][bc0 + q * 4 + j] = h;
                Bl[bkr][bc0 + q * 4 + j] = l;
            }
        }
        __syncthreads();

        // ---- issue next tile's global loads (latency hidden by MMA below) ----
        if (k0 + BKT < K) {
            const float* ap = A + (long long)(bm + arow) * K + (k0 + BKT) + ak0;
            const float* bp = B + (long long)(k0 + BKT + bkr) * N + bn + bc0;
#pragma unroll
            for (int q = 0; q < 4; q++) {
                ra[q] = inM ? *reinterpret_cast<const float4*>(ap + q * 4)
                            : make_float4(0.f, 0.f, 0.f, 0.f);
                rb[q] = *reinterpret_cast<const float4*>(bp + q * 4);
            }
        }

        // ---- compute on current smem tile ----
#pragma unroll
        for (int kk = 0; kk < BKT; kk += 16) {
            unsigned ahi[2][4], alo[2][4];
            int lr = lane & 15;
            int acol = kk + ((lane >> 4) << 3);
#pragma unroll
            for (int mt = 0; mt < 2; mt++) {
                int r = warpM * 32 + mt * 16 + lr;
                unsigned off = (unsigned)(r * ASTR + acol) * 2u;
                ldsm_x4(ahi[mt], a_base_h + off);
                ldsm_x4(alo[mt], a_base_l + off);
            }
            int kr = kk + (lane & 15);
#pragma unroll
            for (int nt = 0; nt < 8; nt++) {
                int n0 = warpN * 64 + nt * 8;
                unsigned boff = (unsigned)(kr * BSTR + n0) * 2u;
                unsigned bh0, bh1, bl0, bl1;
                ldsm_x2t(bh0, bh1, b_base_h + boff);
                ldsm_x2t(bl0, bl1, b_base_l + boff);
#pragma unroll
                for (int mt = 0; mt < 2; mt++) {
                    mma_f16(acc[mt][nt], ahi[mt], bh0, bh1);
                    mma_f16(acc[mt][nt], ahi[mt], bl0, bl1);
                    mma_f16(acc[mt][nt], alo[mt], bh0, bh1);
                }
            }
        }
        __syncthreads();
    }

    // ---- epilogue: write C and accumulate column stats ----
    float cs[16], cq[16];
#pragma unroll
    for (int i = 0; i < 16; i++) { cs[i] = 0.f; cq[i] = 0.f; }

#pragma unroll
    for (int mt = 0; mt < 2; mt++) {
#pragma unroll
        for (int half = 0; half < 2; half++) {
            int row = bm + warpM * 32 + mt * 16 + (lane >> 2) + half * 8;
            if (row >= M) continue;
#pragma unroll
            for (int nt = 0; nt < 8; nt++) {
                int col = bn + warpN * 64 + nt * 8 + (lane & 3) * 2;
                float v0 = acc[mt][nt][half * 2 + 0];
                float v1 = acc[mt][nt][half * 2 + 1];
                if (bias) { v0 += bias[col]; v1 += bias[col + 1]; }
                *reinterpret_cast<float2*>(C + (long long)row * N + col) =
                    make_float2(v0, v1);
                if (statSum) {
                    cs[nt * 2]     += v0; cq[nt * 2]     += v0 * v0;
                    cs[nt * 2 + 1] += v1; cq[nt * 2 + 1] += v1 * v1;
                }
            }
        }
    }
    if (statSum) {
#pragma unroll
        for (int i = 0; i < 16; i++) {
#pragma unroll
            for (int s = 4; s < 32; s <<= 1) {
                cs[i] += __shfl_xor_sync(0xffffffffu, cs[i], s);
                cq[i] += __shfl_xor_sync(0xffffffffu, cq[i], s);
            }
        }
        if (lane < 4) {
#pragma unroll
            for (int nt = 0; nt < 8; nt++) {
                int col = bn + warpN * 64 + nt * 8 + lane * 2;
                atomicAdd(&statSum[col],     cs[nt * 2]);
                atomicAdd(&statSq[col],      cq[nt * 2]);
                atomicAdd(&statSum[col + 1], cs[nt * 2 + 1]);
                atomicAdd(&statSq[col + 1],  cq[nt * 2 + 1]);
            }
        }
    }
}

// -------- bn coefs --------
__global__ void bn_coef_kernel(const float* __restrict__ sum, const float* __restrict__ sumsq,
                               const float* __restrict__ g, const float* __restrict__ beta) {
    int f = threadIdx.x;
    float invN = 1.0f / (float)NN;
    float mu = sum[f] * invN;
    float var = fmaxf(sumsq[f] * invN - mu * mu, 0.0f);
    float s = g[f] * rsqrtf(var + EPS);
    g_bna[f] = s;
    g_bnc[f] = beta[f] - s * mu;
}

// -------- segmented max pool over sorted batch, bn2+lrelu fused --------
__global__ __launch_bounds__(128)
void pool_seg_kernel(const float* __restrict__ P2) {
    int g = blockIdx.x;
    int f = threadIdx.x * 4;
    int s = g_gstart[g], e = g_gend[g];
    float4 a = *reinterpret_cast<const float4*>(g_bna + f);
    float4 c = *reinterpret_cast<const float4*>(g_bnc + f);
    float m0 = -INFINITY, m1 = -INFINITY, m2 = -INFINITY, m3 = -INFINITY;
    for (int r = s; r < e; r++) {
        float4 v = *reinterpret_cast<const float4*>(P2 + (long long)r * HH + f);
        float z0 = fmaf(a.x, v.x, c.x);
        float z1 = fmaf(a.y, v.y, c.y);
        float z2 = fmaf(a.z, v.z, c.z);
        float z3 = fmaf(a.w, v.w, c.w);
        z0 = z0 > 0.f ? z0 : SLOPE * z0;
        z1 = z1 > 0.f ? z1 : SLOPE * z1;
        z2 = z2 > 0.f ? z2 : SLOPE * z2;
        z3 = z3 > 0.f ? z3 : SLOPE * z3;
        m0 = fmaxf(m0, z0); m1 = fmaxf(m1, z1);
        m2 = fmaxf(m2, z2); m3 = fmaxf(m3, z3);
    }
    float4 o;
    if (e <= s) o = make_float4(0.f, 0.f, 0.f, 0.f);
    else        o = make_float4(m0, m1, m2, m3);
    *reinterpret_cast<float4*>(g_pooled + (long long)g * HH + f) = o;
}

// -------- host launch --------
extern "C" void kernel_launch(void* const* d_in, const int* in_sizes, int n_in,
                              void* d_out, int out_size) {
    const float* x      = (const float*)d_in[0];
    const int*   ei     = (const int*)d_in[1];
    const int*   bt     = (const int*)d_in[2];
    const float* W1     = (const float*)d_in[3];
    const float* b1     = (const float*)d_in[4];
    const float* g1     = (const float*)d_in[5];
    const float* beta1  = (const float*)d_in[6];
    const float* W2     = (const float*)d_in[7];
    const float* b2     = (const float*)d_in[8];
    const float* g2     = (const float*)d_in[9];
    const float* beta2  = (const float*)d_in[10];
    const float* Wf     = (const float*)d_in[11];
    const float* bf     = (const float*)d_in[12];
    float* out = (float*)d_out;

    const int* erow = ei;
    const int* ecol = ei + EE;

    float *buf1, *buf2, *buf3, *pooled, *stats;
    cudaGetSymbolAddress((void**)&buf1, g_buf1);
    cudaGetSymbolAddress((void**)&buf2, g_buf2);
    cudaGetSymbolAddress((void**)&buf3, g_buf3);
    cudaGetSymbolAddress((void**)&pooled, g_pooled);
    cudaGetSymbolAddress((void**)&stats, g_stats);

    const int T = 256;
    init_kernel<<<(NN + T - 1) / T, T>>>();
    count_deg_kernel<<<(EE + T - 1) / T, T>>>(ecol);
    scan_kernel<<<1, 1024>>>();
    dinv_kernel<<<(NN + T - 1) / T, T>>>();
    edge_fill_kernel<<<(EE + T - 1) / T, T>>>(erow, ecol);
    seg_bounds_kernel<<<(NN + T - 1) / T, T>>>(bt);

    int blk_gx = (int)(((long long)NN * 32 + T - 1) / T);
    int blk_gz = (int)(((long long)NN * 128 + T - 1) / T);

    // ---- layer 1: gather X, GEMM (+stats1 fused) ----
    gather_x_kernel<<<blk_gx, T>>>(x, buf2);
    {
        dim3 grid(HH / BN, (NN + BM - 1) / BM);
        gemm_f16s<<<grid, 256>>>(buf2, W1, b1, buf1, stats + 0, stats + HH,
                                 NN, HH, DINF);
    }
    bn_coef_kernel<<<1, HH>>>(stats + 0, stats + HH, g1, beta1);

    // ---- layer 2: gather Z (bn1 inline), GEMM (+stats2 fused) ----
    gather_z_kernel<<<blk_gz, T>>>(buf1, buf2);
    {
        dim3 grid(HH / BN, (NN + BM - 1) / BM);
        gemm_f16s<<<grid, 256>>>(buf2, W2, b2, buf3, stats + 2 * HH, stats + 3 * HH,
                                 NN, HH, HH);
    }
    bn_coef_kernel<<<1, HH>>>(stats + 2 * HH, stats + 3 * HH, g2, beta2);

    // ---- segmented pool (bn2+lrelu fused) + final linear ----
    pool_seg_kernel<<<GG, 128>>>(buf3);
    {
        dim3 grid(OUTC / BN, (GG + BM - 1) / BM);
        gemm_f16s<<<grid, 256>>>(pooled, Wf, bf, out, nullptr, nullptr,
                                 GG, OUTC, HH);
    }
}

// round 15
// speedup vs baseline: 3.5107x; 1.1475x over previous
#include <cuda_runtime.h>
#include <cuda_fp16.h>
#include <math.h>

#define NN   100000
#define EE   300000
#define DINF 128
#define HH   512
#define GG   4096
#define OUTC 256
#define SLOPE 0.01f
#define EPS   1e-5f

// -------- scratch (device globals: allocation-free, 256B aligned) --------
__device__ __align__(256) int      g_cnt[NN];
__device__ __align__(256) int      g_cur[NN];
__device__ __align__(256) int      g_off[NN + 1];
__device__ __align__(256) int      g_srow[EE];
__device__ __align__(256) float    g_snorm[EE];
__device__ __align__(256) float    g_selfc[NN];
__device__ __align__(256) float    g_dinv[NN];
__device__ __align__(256) int      g_gstart[GG];
__device__ __align__(256) int      g_gend[GG];
__device__ __align__(256) float    g_buf1[(size_t)NN * HH];   // P1
__device__ __align__(256) float    g_buf3[(size_t)NN * HH];   // P2
__device__ __align__(256) __half   g_xah[(size_t)NN * DINF];  // Xa hi
__device__ __align__(256) __half   g_xal[(size_t)NN * DINF];  // Xa lo
__device__ __align__(256) __half   g_zah[(size_t)NN * HH];    // Za hi
__device__ __align__(256) __half   g_zal[(size_t)NN * HH];    // Za lo
__device__ __align__(256) __half   g_plh[(size_t)GG * HH];    // pooled hi
__device__ __align__(256) __half   g_pll[(size_t)GG * HH];    // pooled lo
__device__ __align__(256) __half   g_w1h[(size_t)DINF * HH], g_w1l[(size_t)DINF * HH];
__device__ __align__(256) __half   g_w2h[(size_t)HH * HH],   g_w2l[(size_t)HH * HH];
__device__ __align__(256) __half   g_wfh[(size_t)HH * OUTC], g_wfl[(size_t)HH * OUTC];
__device__ __align__(256) float    g_stats[4 * HH];
__device__ __align__(256) float    g_bna[HH];
__device__ __align__(256) float    g_bnc[HH];

// -------- init --------
__global__ void init_kernel() {
    int i = blockIdx.x * blockDim.x + threadIdx.x;
    if (i < NN) { g_cnt[i] = 0; g_cur[i] = 0; }
    if (i < GG) { g_gstart[i] = 0; g_gend[i] = 0; }
    if (i < 4 * HH) g_stats[i] = 0.0f;
}

__global__ void count_deg_kernel(const int* __restrict__ ecol) {
    int e = blockIdx.x * blockDim.x + threadIdx.x;
    if (e < EE) atomicAdd(&g_cnt[ecol[e]], 1);
}

// single-block scan, 4 elements/thread (25 iterations over 100k)
__global__ void scan_kernel() {
    __shared__ int sh[1024];
    __shared__ int carry;
    int t = threadIdx.x;
    if (t == 0) carry = 0;
    __syncthreads();
    for (int base = 0; base < NN; base += 4096) {
        int i0 = base + t * 4;
        int v[4];
#pragma unroll
        for (int j = 0; j < 4; j++) v[j] = (i0 + j < NN) ? g_cnt[i0 + j] : 0;
        int tsum = v[0] + v[1] + v[2] + v[3];
        sh[t] = tsum;
        __syncthreads();
        for (int s = 1; s < 1024; s <<= 1) {
            int add = (t >= s) ? sh[t - s] : 0;
            __syncthreads();
            sh[t] += add;
            __syncthreads();
        }
        int run = carry + sh[t] - tsum;   // exclusive prefix for this thread's chunk
#pragma unroll
        for (int j = 0; j < 4; j++) {
            if (i0 + j < NN) { g_off[i0 + j] = run; run += v[j]; }
        }
        int total = sh[1023];
        __syncthreads();
        if (t == 0) carry += total;
        __syncthreads();
    }
    if (t == 0) g_off[NN] = carry;
}

__global__ void dinv_kernel() {
    int i = blockIdx.x * blockDim.x + threadIdx.x;
    if (i < NN) {
        float d = (float)g_cnt[i] + 2.0f;
        float di = rsqrtf(d);
        g_dinv[i] = di;
        g_selfc[i] = 2.0f * di * di;
    }
}

__global__ void edge_fill_kernel(const int* __restrict__ erow,
                                 const int* __restrict__ ecol) {
    int e = blockIdx.x * blockDim.x + threadIdx.x;
    if (e >= EE) return;
    int r = erow[e];
    int c = ecol[e];
    int pos = g_off[c] + atomicAdd(&g_cur[c], 1);
    g_srow[pos] = r;
    g_snorm[pos] = g_dinv[r] * g_dinv[c];
}

__global__ void seg_bounds_kernel(const int* __restrict__ bt) {
    int i = blockIdx.x * blockDim.x + threadIdx.x;
    if (i >= NN) return;
    int b = bt[i];
    if (i == 0 || bt[i - 1] != b) g_gstart[b] = i;
    if (i == NN - 1 || bt[i + 1] != b) g_gend[b] = i + 1;
}

// -------- weight split (once per call, [k][n] layout preserved) --------
__global__ void wsplit_kernel(const float* __restrict__ W, __half* __restrict__ Wh,
                              __half* __restrict__ Wl, int total) {
    int i = blockIdx.x * blockDim.x + threadIdx.x;
    if (i >= total) return;
    float v = W[i];
    __half h = __float2half_rn(v);
    Wh[i] = h;
    Wl[i] = __float2half_rn(v - __half2float(h));
}

__device__ __forceinline__ void split_store4(__half* __restrict__ Hd,
                                             __half* __restrict__ Ld,
                                             long long base, const float* v) {
    __half h[4], l[4];
#pragma unroll
    for (int j = 0; j < 4; j++) {
        h[j] = __float2half_rn(v[j]);
        l[j] = __float2half_rn(v[j] - __half2float(h[j]));
    }
    *reinterpret_cast<__half2*>(&Hd[base])     = __halves2half2(h[0], h[1]);
    *reinterpret_cast<__half2*>(&Hd[base + 2]) = __halves2half2(h[2], h[3]);
    *reinterpret_cast<__half2*>(&Ld[base])     = __halves2half2(l[0], l[1]);
    *reinterpret_cast<__half2*>(&Ld[base + 2]) = __halves2half2(l[2], l[3]);
}

// -------- layer-1 gather (W=128), emits fp16 hi/lo --------
__global__ void gather_x_kernel(const float* __restrict__ x) {
    long long gid = (long long)blockIdx.x * blockDim.x + threadIdx.x;
    int node = (int)(gid >> 5);
    int f = (int)(gid & 31) * 4;
    if (node >= NN) return;
    int s = g_off[node], epd = g_off[node + 1];
    float sc = g_selfc[node];
    float4 v = *reinterpret_cast<const float4*>(x + (long long)node * DINF + f);
    float4 acc = make_float4(v.x * sc, v.y * sc, v.z * sc, v.w * sc);
#pragma unroll 4
    for (int e = s; e < epd; e++) {
        int r = g_srow[e];
        float nm = g_snorm[e];
        float4 u = *reinterpret_cast<const float4*>(x + (long long)r * DINF + f);
        acc.x = fmaf(nm, u.x, acc.x);
        acc.y = fmaf(nm, u.y, acc.y);
        acc.z = fmaf(nm, u.z, acc.z);
        acc.w = fmaf(nm, u.w, acc.w);
    }
    float vv[4] = {acc.x, acc.y, acc.z, acc.w};
    split_store4(g_xah, g_xal, (long long)node * DINF + f, vv);
}

// -------- layer-2 gather on Z = lrelu(bn1(P1)), emits fp16 hi/lo --------
__device__ __forceinline__ float4 zval(const float* __restrict__ P1, int row, int f) {
    float4 v = *reinterpret_cast<const float4*>(P1 + (long long)row * HH + f);
    float4 a = *reinterpret_cast<const float4*>(g_bna + f);
    float4 c = *reinterpret_cast<const float4*>(g_bnc + f);
    float4 z;
    z.x = fmaf(a.x, v.x, c.x); z.y = fmaf(a.y, v.y, c.y);
    z.z = fmaf(a.z, v.z, c.z); z.w = fmaf(a.w, v.w, c.w);
    z.x = z.x > 0.f ? z.x : SLOPE * z.x;
    z.y = z.y > 0.f ? z.y : SLOPE * z.y;
    z.z = z.z > 0.f ? z.z : SLOPE * z.z;
    z.w = z.w > 0.f ? z.w : SLOPE * z.w;
    return z;
}

__global__ void gather_z_kernel(const float* __restrict__ P1) {
    long long gid = (long long)blockIdx.x * blockDim.x + threadIdx.x;
    int node = (int)(gid >> 7);
    int f = (int)(gid & 127) * 4;
    if (node >= NN) return;
    int s = g_off[node], epd = g_off[node + 1];
    float sc = g_selfc[node];
    float4 z = zval(P1, node, f);
    float4 acc = make_float4(z.x * sc, z.y * sc, z.z * sc, z.w * sc);
#pragma unroll 4
    for (int e = s; e < epd; e++) {
        int r = g_srow[e];
        float nm = g_snorm[e];
        float4 u = zval(P1, r, f);
        acc.x = fmaf(nm, u.x, acc.x);
        acc.y = fmaf(nm, u.y, acc.y);
        acc.z = fmaf(nm, u.z, acc.z);
        acc.w = fmaf(nm, u.w, acc.w);
    }
    float vv[4] = {acc.x, acc.y, acc.z, acc.w};
    split_store4(g_zah, g_zal, (long long)node * HH + f, vv);
}

// -------- FP16 pre-split GEMM (mma.sync, copy-only staging, fused stats) ----
#define BM 128
#define BN 128
#define BKT 32
#define ASTR 56
#define BSTR 136

__device__ __forceinline__ void mma_f16(float c[4], const unsigned a[4],
                                        unsigned b0, unsigned b1) {
    asm("mma.sync.aligned.m16n8k16.row.col.f32.f16.f16.f32 "
        "{%0,%1,%2,%3},{%4,%5,%6,%7},{%8,%9},{%0,%1,%2,%3};"
        : "+f"(c[0]), "+f"(c[1]), "+f"(c[2]), "+f"(c[3])
        : "r"(a[0]), "r"(a[1]), "r"(a[2]), "r"(a[3]), "r"(b0), "r"(b1));
}

__device__ __forceinline__ void ldsm_x4(unsigned r[4], unsigned saddr) {
    asm volatile("ldmatrix.sync.aligned.m8n8.x4.shared.b16 {%0,%1,%2,%3}, [%4];"
                 : "=r"(r[0]), "=r"(r[1]), "=r"(r[2]), "=r"(r[3]) : "r"(saddr));
}

__device__ __forceinline__ void ldsm_x2t(unsigned &r0, unsigned &r1, unsigned saddr) {
    asm volatile("ldmatrix.sync.aligned.m8n8.x2.trans.shared.b16 {%0,%1}, [%2];"
                 : "=r"(r0), "=r"(r1) : "r"(saddr));
}

__global__ __launch_bounds__(256)
void gemm_f16p(const __half* __restrict__ Agh, const __half* __restrict__ Agl,
               const __half* __restrict__ Bgh, const __half* __restrict__ Bgl,
               const float* __restrict__ bias, float* __restrict__ C,
               float* __restrict__ statSum, float* __restrict__ statSq,
               int M, int N, int K) {
    __shared__ __align__(16) __half Ah[BM][ASTR], Al[BM][ASTR];
    __shared__ __align__(16) __half Bh[BKT][BSTR], Bl[BKT][BSTR];

    int tid  = threadIdx.x;
    int lane = tid & 31;
    int warp = tid >> 5;
    int warpM = warp & 3;
    int warpN = warp >> 2;
    int bm = blockIdx.y * BM;
    int bn = blockIdx.x * BN;

    float acc[2][8][4];
#pragma unroll
    for (int i = 0; i < 2; i++)
#pragma unroll
        for (int j = 0; j < 8; j++)
#pragma unroll
            for (int r = 0; r < 4; r++) acc[i][j][r] = 0.0f;

    int arow = tid >> 1;
    int ak0  = (tid & 1) * 16;
    int bkr  = tid >> 3;
    int bc0  = (tid & 7) * 16;
    bool inM = (bm + arow < M);

    unsigned a_base_h = (unsigned)__cvta_generic_to_shared(&Ah[0][0]);
    unsigned a_base_l = (unsigned)__cvta_generic_to_shared(&Al[0][0]);
    unsigned b_base_h = (unsigned)__cvta_generic_to_shared(&Bh[0][0]);
    unsigned b_base_l = (unsigned)__cvta_generic_to_shared(&Bl[0][0]);

    uint4 rah[2], ral[2], rbh[2], rbl[2];
    const uint4 zero4 = make_uint4(0, 0, 0, 0);

    // prefetch k0=0
    {
        size_t aoff = (size_t)(bm + arow) * K + ak0;
        size_t boff = (size_t)bkr * N + bn + bc0;
        rah[0] = inM ? *reinterpret_cast<const uint4*>(Agh + aoff) : zero4;
        rah[1] = inM ? *reinterpret_cast<const uint4*>(Agh + aoff + 8) : zero4;
        ral[0] = inM ? *reinterpret_cast<const uint4*>(Agl + aoff) : zero4;
        ral[1] = inM ? *reinterpret_cast<const uint4*>(Agl + aoff + 8) : zero4;
        rbh[0] = *reinterpret_cast<const uint4*>(Bgh + boff);
        rbh[1] = *reinterpret_cast<const uint4*>(Bgh + boff + 8);
        rbl[0] = *reinterpret_cast<const uint4*>(Bgl + boff);
        rbl[1] = *reinterpret_cast<const uint4*>(Bgl + boff + 8);
    }

    for (int k0 = 0; k0 < K; k0 += BKT) {
        // store staged tile (pure copies)
        *reinterpret_cast<uint4*>(&Ah[arow][ak0])     = rah[0];
        *reinterpret_cast<uint4*>(&Ah[arow][ak0 + 8]) = rah[1];
        *reinterpret_cast<uint4*>(&Al[arow][ak0])     = ral[0];
        *reinterpret_cast<uint4*>(&Al[arow][ak0 + 8]) = ral[1];
        *reinterpret_cast<uint4*>(&Bh[bkr][bc0])      = rbh[0];
        *reinterpret_cast<uint4*>(&Bh[bkr][bc0 + 8])  = rbh[1];
        *reinterpret_cast<uint4*>(&Bl[bkr][bc0])      = rbl[0];
        *reinterpret_cast<uint4*>(&Bl[bkr][bc0 + 8])  = rbl[1];
        __syncthreads();

        // prefetch next tile
        if (k0 + BKT < K) {
            size_t aoff = (size_t)(bm + arow) * K + (k0 + BKT) + ak0;
            size_t boff = (size_t)(k0 + BKT + bkr) * N + bn + bc0;
            rah[0] = inM ? *reinterpret_cast<const uint4*>(Agh + aoff) : zero4;
            rah[1] = inM ? *reinterpret_cast<const uint4*>(Agh + aoff + 8) : zero4;
            ral[0] = inM ? *reinterpret_cast<const uint4*>(Agl + aoff) : zero4;
            ral[1] = inM ? *reinterpret_cast<const uint4*>(Agl + aoff + 8) : zero4;
            rbh[0] = *reinterpret_cast<const uint4*>(Bgh + boff);
            rbh[1] = *reinterpret_cast<const uint4*>(Bgh + boff + 8);
            rbl[0] = *reinterpret_cast<const uint4*>(Bgl + boff);
            rbl[1] = *reinterpret_cast<const uint4*>(Bgl + boff + 8);
        }

        // compute
#pragma unroll
        for (int kk = 0; kk < BKT; kk += 16) {
            unsigned ahi[2][4], alo[2][4];
            int lr = lane & 15;
            int acol = kk + ((lane >> 4) << 3);
#pragma unroll
            for (int mt = 0; mt < 2; mt++) {
                int r = warpM * 32 + mt * 16 + lr;
                unsigned off = (unsigned)(r * ASTR + acol) * 2u;
                ldsm_x4(ahi[mt], a_base_h + off);
                ldsm_x4(alo[mt], a_base_l + off);
            }
            int kr = kk + (lane & 15);
#pragma unroll
            for (int nt = 0; nt < 8; nt++) {
                int n0 = warpN * 64 + nt * 8;
                unsigned boff2 = (unsigned)(kr * BSTR + n0) * 2u;
                unsigned bh0, bh1, bl0, bl1;
                ldsm_x2t(bh0, bh1, b_base_h + boff2);
                ldsm_x2t(bl0, bl1, b_base_l + boff2);
#pragma unroll
                for (int mt = 0; mt < 2; mt++) {
                    mma_f16(acc[mt][nt], ahi[mt], bh0, bh1);
                    mma_f16(acc[mt][nt], ahi[mt], bl0, bl1);
                    mma_f16(acc[mt][nt], alo[mt], bh0, bh1);
                }
            }
        }
        __syncthreads();
    }

    // ---- epilogue: write C + fused column stats ----
    float cs[16], cq[16];
#pragma unroll
    for (int i = 0; i < 16; i++) { cs[i] = 0.f; cq[i] = 0.f; }

#pragma unroll
    for (int mt = 0; mt < 2; mt++) {
#pragma unroll
        for (int half = 0; half < 2; half++) {
            int row = bm + warpM * 32 + mt * 16 + (lane >> 2) + half * 8;
            if (row >= M) continue;
#pragma unroll
            for (int nt = 0; nt < 8; nt++) {
                int col = bn + warpN * 64 + nt * 8 + (lane & 3) * 2;
                float v0 = acc[mt][nt][half * 2 + 0];
                float v1 = acc[mt][nt][half * 2 + 1];
                if (bias) { v0 += bias[col]; v1 += bias[col + 1]; }
                *reinterpret_cast<float2*>(C + (long long)row * N + col) =
                    make_float2(v0, v1);
                if (statSum) {
                    cs[nt * 2]     += v0; cq[nt * 2]     += v0 * v0;
                    cs[nt * 2 + 1] += v1; cq[nt * 2 + 1] += v1 * v1;
                }
            }
        }
    }
    if (statSum) {
#pragma unroll
        for (int i = 0; i < 16; i++) {
#pragma unroll
            for (int s = 4; s < 32; s <<= 1) {
                cs[i] += __shfl_xor_sync(0xffffffffu, cs[i], s);
                cq[i] += __shfl_xor_sync(0xffffffffu, cq[i], s);
            }
        }
        if (lane < 4) {
#pragma unroll
            for (int nt = 0; nt < 8; nt++) {
                int col = bn + warpN * 64 + nt * 8 + lane * 2;
                atomicAdd(&statSum[col],     cs[nt * 2]);
                atomicAdd(&statSq[col],      cq[nt * 2]);
                atomicAdd(&statSum[col + 1], cs[nt * 2 + 1]);
                atomicAdd(&statSq[col + 1],  cq[nt * 2 + 1]);
            }
        }
    }
}

// -------- bn coefs --------
__global__ void bn_coef_kernel(const float* __restrict__ sum, const float* __restrict__ sumsq,
                               const float* __restrict__ g, const float* __restrict__ beta) {
    int f = threadIdx.x;
    float invN = 1.0f / (float)NN;
    float mu = sum[f] * invN;
    float var = fmaxf(sumsq[f] * invN - mu * mu, 0.0f);
    float s = g[f] * rsqrtf(var + EPS);
    g_bna[f] = s;
    g_bnc[f] = beta[f] - s * mu;
}

// -------- segmented max pool (sorted batch), bn2+lrelu fused, fp16 hi/lo out --
__global__ __launch_bounds__(128)
void pool_seg_kernel(const float* __restrict__ P2) {
    int g = blockIdx.x;
    int f = threadIdx.x * 4;
    int s = g_gstart[g], e = g_gend[g];
    float4 a = *reinterpret_cast<const float4*>(g_bna + f);
    float4 c = *reinterpret_cast<const float4*>(g_bnc + f);
    float m0 = -INFINITY, m1 = -INFINITY, m2 = -INFINITY, m3 = -INFINITY;
    for (int r = s; r < e; r++) {
        float4 v = *reinterpret_cast<const float4*>(P2 + (long long)r * HH + f);
        float z0 = fmaf(a.x, v.x, c.x);
        float z1 = fmaf(a.y, v.y, c.y);
        float z2 = fmaf(a.z, v.z, c.z);
        float z3 = fmaf(a.w, v.w, c.w);
        z0 = z0 > 0.f ? z0 : SLOPE * z0;
        z1 = z1 > 0.f ? z1 : SLOPE * z1;
        z2 = z2 > 0.f ? z2 : SLOPE * z2;
        z3 = z3 > 0.f ? z3 : SLOPE * z3;
        m0 = fmaxf(m0, z0); m1 = fmaxf(m1, z1);
        m2 = fmaxf(m2, z2); m3 = fmaxf(m3, z3);
    }
    float vv[4];
    if (e <= s) { vv[0] = vv[1] = vv[2] = vv[3] = 0.f; }
    else        { vv[0] = m0; vv[1] = m1; vv[2] = m2; vv[3] = m3; }
    split_store4(g_plh, g_pll, (long long)g * HH + f, vv);
}

// -------- host launch --------
extern "C" void kernel_launch(void* const* d_in, const int* in_sizes, int n_in,
                              void* d_out, int out_size) {
    const float* x      = (const float*)d_in[0];
    const int*   ei     = (const int*)d_in[1];
    const int*   bt     = (const int*)d_in[2];
    const float* W1     = (const float*)d_in[3];
    const float* b1     = (const float*)d_in[4];
    const float* g1     = (const float*)d_in[5];
    const float* beta1  = (const float*)d_in[6];
    const float* W2     = (const float*)d_in[7];
    const float* b2     = (const float*)d_in[8];
    const float* g2     = (const float*)d_in[9];
    const float* beta2  = (const float*)d_in[10];
    const float* Wf     = (const float*)d_in[11];
    const float* bf     = (const float*)d_in[12];
    float* out = (float*)d_out;

    const int* erow = ei;
    const int* ecol = ei + EE;

    float *buf1, *buf3, *stats;
    __half *xah, *xal, *zah, *zal, *plh, *pll;
    __half *w1h, *w1l, *w2h, *w2l, *wfh, *wfl;
    cudaGetSymbolAddress((void**)&buf1, g_buf1);
    cudaGetSymbolAddress((void**)&buf3, g_buf3);
    cudaGetSymbolAddress((void**)&stats, g_stats);
    cudaGetSymbolAddress((void**)&xah, g_xah);
    cudaGetSymbolAddress((void**)&xal, g_xal);
    cudaGetSymbolAddress((void**)&zah, g_zah);
    cudaGetSymbolAddress((void**)&zal, g_zal);
    cudaGetSymbolAddress((void**)&plh, g_plh);
    cudaGetSymbolAddress((void**)&pll, g_pll);
    cudaGetSymbolAddress((void**)&w1h, g_w1h);
    cudaGetSymbolAddress((void**)&w1l, g_w1l);
    cudaGetSymbolAddress((void**)&w2h, g_w2h);
    cudaGetSymbolAddress((void**)&w2l, g_w2l);
    cudaGetSymbolAddress((void**)&wfh, g_wfh);
    cudaGetSymbolAddress((void**)&wfl, g_wfl);

    const int T = 256;
    init_kernel<<<(NN + T - 1) / T, T>>>();
    count_deg_kernel<<<(EE + T - 1) / T, T>>>(ecol);
    wsplit_kernel<<<(DINF * HH + T - 1) / T, T>>>(W1, w1h, w1l, DINF * HH);
    wsplit_kernel<<<(HH * HH + T - 1) / T, T>>>(W2, w2h, w2l, HH * HH);
    wsplit_kernel<<<(HH * OUTC + T - 1) / T, T>>>(Wf, wfh, wfl, HH * OUTC);
    scan_kernel<<<1, 1024>>>();
    dinv_kernel<<<(NN + T - 1) / T, T>>>();
    edge_fill_kernel<<<(EE + T - 1) / T, T>>>(erow, ecol);
    seg_bounds_kernel<<<(NN + T - 1) / T, T>>>(bt);

    int blk_gx = (int)(((long long)NN * 32 + T - 1) / T);
    int blk_gz = (int)(((long long)NN * 128 + T - 1) / T);

    // ---- layer 1: gather X (fp16 split out), GEMM (+stats1 fused) ----
    gather_x_kernel<<<blk_gx, T>>>(x);
    {
        dim3 grid(HH / BN, (NN + BM - 1) / BM);
        gemm_f16p<<<grid, 256>>>(xah, xal, w1h, w1l, b1, buf1,
                                 stats + 0, stats + HH, NN, HH, DINF);
    }
    bn_coef_kernel<<<1, HH>>>(stats + 0, stats + HH, g1, beta1);

    // ---- layer 2: gather Z (fp16 split out), GEMM (+stats2 fused) ----
    gather_z_kernel<<<blk_gz, T>>>(buf1);
    {
        dim3 grid(HH / BN, (NN + BM - 1) / BM);
        gemm_f16p<<<grid, 256>>>(zah, zal, w2h, w2l, b2, buf3,
                                 stats + 2 * HH, stats + 3 * HH, NN, HH, HH);
    }
    bn_coef_kernel<<<1, HH>>>(stats + 2 * HH, stats + 3 * HH, g2, beta2);

    // ---- segmented pool (bn2+lrelu fused, fp16 split out) + final GEMM ----
    pool_seg_kernel<<<GG, 128>>>(buf3);
    {
        dim3 grid(OUTC / BN, (GG + BM - 1) / BM);
        gemm_f16p<<<grid, 256>>>(plh, pll, wfh, wfl, bf, out,
                                 nullptr, nullptr, GG, OUTC, HH);
    }
}

// round 17
// speedup vs baseline: 4.6780x; 1.3325x over previous
#include <cuda_runtime.h>
#include <cuda_fp16.h>
#include <math.h>

#define NN   100000
#define EE   300000
#define DINF 128
#define HH   512
#define GG   4096
#define OUTC 256
#define SLOPE 0.01f
#define EPS   1e-5f

// -------- scratch (device globals: allocation-free, 256B aligned) --------
__device__ __align__(256) int      g_cnt[NN];
__device__ __align__(256) int      g_cur[NN];
__device__ __align__(256) int      g_off[NN + 1];
__device__ __align__(256) int      g_srow[EE];
__device__ __align__(256) float    g_snorm[EE];
__device__ __align__(256) float    g_selfc[NN];
__device__ __align__(256) float    g_dinv[NN];
__device__ __align__(256) int      g_gstart[GG];
__device__ __align__(256) int      g_gend[GG];
__device__ __align__(256) float    g_buf1[(size_t)NN * HH];   // P1
__device__ __align__(256) float    g_buf3[(size_t)NN * HH];   // P2
__device__ __align__(256) __half   g_xah[(size_t)NN * DINF];  // Xa (fp16)
__device__ __align__(256) __half   g_zah[(size_t)NN * HH];    // Za (fp16)
__device__ __align__(256) __half   g_plh[(size_t)GG * HH];    // pooled (fp16)
__device__ __align__(256) __half   g_w1h[(size_t)DINF * HH], g_w1l[(size_t)DINF * HH];
__device__ __align__(256) __half   g_w2h[(size_t)HH * HH],   g_w2l[(size_t)HH * HH];
__device__ __align__(256) __half   g_wfh[(size_t)HH * OUTC], g_wfl[(size_t)HH * OUTC];
__device__ __align__(256) float    g_stats[4 * HH];
__device__ __align__(256) float    g_bna[HH];
__device__ __align__(256) float    g_bnc[HH];

// -------- init --------
__global__ void init_kernel() {
    int i = blockIdx.x * blockDim.x + threadIdx.x;
    if (i < NN) { g_cnt[i] = 0; g_cur[i] = 0; }
    if (i < GG) { g_gstart[i] = 0; g_gend[i] = 0; }
    if (i < 4 * HH) g_stats[i] = 0.0f;
}

__global__ void count_deg_kernel(const int* __restrict__ ecol) {
    int e = blockIdx.x * blockDim.x + threadIdx.x;
    if (e < EE) atomicAdd(&g_cnt[ecol[e]], 1);
}

// single-block scan, 4 elements/thread
__global__ void scan_kernel() {
    __shared__ int sh[1024];
    __shared__ int carry;
    int t = threadIdx.x;
    if (t == 0) carry = 0;
    __syncthreads();
    for (int base = 0; base < NN; base += 4096) {
        int i0 = base + t * 4;
        int v[4];
#pragma unroll
        for (int j = 0; j < 4; j++) v[j] = (i0 + j < NN) ? g_cnt[i0 + j] : 0;
        int tsum = v[0] + v[1] + v[2] + v[3];
        sh[t] = tsum;
        __syncthreads();
        for (int s = 1; s < 1024; s <<= 1) {
            int add = (t >= s) ? sh[t - s] : 0;
            __syncthreads();
            sh[t] += add;
            __syncthreads();
        }
        int run = carry + sh[t] - tsum;
#pragma unroll
        for (int j = 0; j < 4; j++) {
            if (i0 + j < NN) { g_off[i0 + j] = run; run += v[j]; }
        }
        int total = sh[1023];
        __syncthreads();
        if (t == 0) carry += total;
        __syncthreads();
    }
    if (t == 0) g_off[NN] = carry;
}

__global__ void dinv_kernel() {
    int i = blockIdx.x * blockDim.x + threadIdx.x;
    if (i < NN) {
        float d = (float)g_cnt[i] + 2.0f;
        float di = rsqrtf(d);
        g_dinv[i] = di;
        g_selfc[i] = 2.0f * di * di;
    }
}

__global__ void edge_fill_kernel(const int* __restrict__ erow,
                                 const int* __restrict__ ecol) {
    int e = blockIdx.x * blockDim.x + threadIdx.x;
    if (e >= EE) return;
    int r = erow[e];
    int c = ecol[e];
    int pos = g_off[c] + atomicAdd(&g_cur[c], 1);
    g_srow[pos] = r;
    g_snorm[pos] = g_dinv[r] * g_dinv[c];
}

__global__ void seg_bounds_kernel(const int* __restrict__ bt) {
    int i = blockIdx.x * blockDim.x + threadIdx.x;
    if (i >= NN) return;
    int b = bt[i];
    if (i == 0 || bt[i - 1] != b) g_gstart[b] = i;
    if (i == NN - 1 || bt[i + 1] != b) g_gend[b] = i + 1;
}

// -------- weight split hi/lo (B-side keeps 2-level precision) --------
__global__ void wsplit_kernel(const float* __restrict__ W, __half* __restrict__ Wh,
                              __half* __restrict__ Wl, int total) {
    int i = blockIdx.x * blockDim.x + threadIdx.x;
    if (i >= total) return;
    float v = W[i];
    __half h = __float2half_rn(v);
    Wh[i] = h;
    Wl[i] = __float2half_rn(v - __half2float(h));
}

__device__ __forceinline__ void round_store4(__half* __restrict__ Hd,
                                             long long base, const float* v) {
    __half h[4];
#pragma unroll
    for (int j = 0; j < 4; j++) h[j] = __float2half_rn(v[j]);
    *reinterpret_cast<__half2*>(&Hd[base])     = __halves2half2(h[0], h[1]);
    *reinterpret_cast<__half2*>(&Hd[base + 2]) = __halves2half2(h[2], h[3]);
}

// -------- layer-1 gather (W=128), emits fp16 --------
__global__ void gather_x_kernel(const float* __restrict__ x) {
    long long gid = (long long)blockIdx.x * blockDim.x + threadIdx.x;
    int node = (int)(gid >> 5);
    int f = (int)(gid & 31) * 4;
    if (node >= NN) return;
    int s = g_off[node], epd = g_off[node + 1];
    float sc = g_selfc[node];
    float4 v = *reinterpret_cast<const float4*>(x + (long long)node * DINF + f);
    float4 acc = make_float4(v.x * sc, v.y * sc, v.z * sc, v.w * sc);
#pragma unroll 4
    for (int e = s; e < epd; e++) {
        int r = g_srow[e];
        float nm = g_snorm[e];
        float4 u = *reinterpret_cast<const float4*>(x + (long long)r * DINF + f);
        acc.x = fmaf(nm, u.x, acc.x);
        acc.y = fmaf(nm, u.y, acc.y);
        acc.z = fmaf(nm, u.z, acc.z);
        acc.w = fmaf(nm, u.w, acc.w);
    }
    float vv[4] = {acc.x, acc.y, acc.z, acc.w};
    round_store4(g_xah, (long long)node * DINF + f, vv);
}

// -------- layer-2 gather on Z = lrelu(bn1(P1)), emits fp16 --------
__device__ __forceinline__ float4 zval(const float* __restrict__ P1, int row, int f) {
    float4 v = *reinterpret_cast<const float4*>(P1 + (long long)row * HH + f);
    float4 a = *reinterpret_cast<const float4*>(g_bna + f);
    float4 c = *reinterpret_cast<const float4*>(g_bnc + f);
    float4 z;
    z.x = fmaf(a.x, v.x, c.x); z.y = fmaf(a.y, v.y, c.y);
    z.z = fmaf(a.z, v.z, c.z); z.w = fmaf(a.w, v.w, c.w);
    z.x = z.x > 0.f ? z.x : SLOPE * z.x;
    z.y = z.y > 0.f ? z.y : SLOPE * z.y;
    z.z = z.z > 0.f ? z.z : SLOPE * z.z;
    z.w = z.w > 0.f ? z.w : SLOPE * z.w;
    return z;
}

__global__ void gather_z_kernel(const float* __restrict__ P1) {
    long long gid = (long long)blockIdx.x * blockDim.x + threadIdx.x;
    int node = (int)(gid >> 7);
    int f = (int)(gid & 127) * 4;
    if (node >= NN) return;
    int s = g_off[node], epd = g_off[node + 1];
    float sc = g_selfc[node];
    float4 z = zval(P1, node, f);
    float4 acc = make_float4(z.x * sc, z.y * sc, z.z * sc, z.w * sc);
#pragma unroll 4
    for (int e = s; e < epd; e++) {
        int r = g_srow[e];
        float nm = g_snorm[e];
        float4 u = zval(P1, r, f);
        acc.x = fmaf(nm, u.x, acc.x);
        acc.y = fmaf(nm, u.y, acc.y);
        acc.z = fmaf(nm, u.z, acc.z);
        acc.w = fmaf(nm, u.w, acc.w);
    }
    float vv[4] = {acc.x, acc.y, acc.z, acc.w};
    round_store4(g_zah, (long long)node * HH + f, vv);
}

// -------- 2-product fp16 GEMM: A fp16, B hi/lo; copy staging; fused stats ----
#define BM 128
#define BN 128
#define BKT 32
#define ASTR 56
#define BSTR 136

__device__ __forceinline__ void mma_f16(float c[4], const unsigned a[4],
                                        unsigned b0, unsigned b1) {
    asm("mma.sync.aligned.m16n8k16.row.col.f32.f16.f16.f32 "
        "{%0,%1,%2,%3},{%4,%5,%6,%7},{%8,%9},{%0,%1,%2,%3};"
        : "+f"(c[0]), "+f"(c[1]), "+f"(c[2]), "+f"(c[3])
        : "r"(a[0]), "r"(a[1]), "r"(a[2]), "r"(a[3]), "r"(b0), "r"(b1));
}

__device__ __forceinline__ void ldsm_x4(unsigned r[4], unsigned saddr) {
    asm volatile("ldmatrix.sync.aligned.m8n8.x4.shared.b16 {%0,%1,%2,%3}, [%4];"
                 : "=r"(r[0]), "=r"(r[1]), "=r"(r[2]), "=r"(r[3]) : "r"(saddr));
}

__device__ __forceinline__ void ldsm_x4t(unsigned r[4], unsigned saddr) {
    asm volatile("ldmatrix.sync.aligned.m8n8.x4.trans.shared.b16 {%0,%1,%2,%3}, [%4];"
                 : "=r"(r[0]), "=r"(r[1]), "=r"(r[2]), "=r"(r[3]) : "r"(saddr));
}

__global__ __launch_bounds__(256)
void gemm_f16p(const __half* __restrict__ Ag,
               const __half* __restrict__ Bgh, const __half* __restrict__ Bgl,
               const float* __restrict__ bias, float* __restrict__ C,
               float* __restrict__ statSum, float* __restrict__ statSq,
               int M, int N, int K) {
    __shared__ __align__(16) __half Ah[BM][ASTR];
    __shared__ __align__(16) __half Bh[BKT][BSTR], Bl[BKT][BSTR];

    int tid  = threadIdx.x;
    int lane = tid & 31;
    int warp = tid >> 5;
    int warpM = warp & 3;
    int warpN = warp >> 2;
    int bm = blockIdx.y * BM;
    int bn = blockIdx.x * BN;

    float acc[2][8][4];
#pragma unroll
    for (int i = 0; i < 2; i++)
#pragma unroll
        for (int j = 0; j < 8; j++)
#pragma unroll
            for (int r = 0; r < 4; r++) acc[i][j][r] = 0.0f;

    int arow = tid >> 1;
    int ak0  = (tid & 1) * 16;
    int bkr  = tid >> 3;
    int bc0  = (tid & 7) * 16;
    bool inM = (bm + arow < M);

    unsigned a_base   = (unsigned)__cvta_generic_to_shared(&Ah[0][0]);
    unsigned b_base_h = (unsigned)__cvta_generic_to_shared(&Bh[0][0]);
    unsigned b_base_l = (unsigned)__cvta_generic_to_shared(&Bl[0][0]);

    uint4 ra[2], rbh[2], rbl[2];
    const uint4 zero4 = make_uint4(0, 0, 0, 0);

    // prefetch k0=0
    {
        size_t aoff = (size_t)(bm + arow) * K + ak0;
        size_t boff = (size_t)bkr * N + bn + bc0;
        ra[0] = inM ? *reinterpret_cast<const uint4*>(Ag + aoff) : zero4;
        ra[1] = inM ? *reinterpret_cast<const uint4*>(Ag + aoff + 8) : zero4;
        rbh[0] = *reinterpret_cast<const uint4*>(Bgh + boff);
        rbh[1] = *reinterpret_cast<const uint4*>(Bgh + boff + 8);
        rbl[0] = *reinterpret_cast<const uint4*>(Bgl + boff);
        rbl[1] = *reinterpret_cast<const uint4*>(Bgl + boff + 8);
    }

    for (int k0 = 0; k0 < K; k0 += BKT) {
        *reinterpret_cast<uint4*>(&Ah[arow][ak0])     = ra[0];
        *reinterpret_cast<uint4*>(&Ah[arow][ak0 + 8]) = ra[1];
        *reinterpret_cast<uint4*>(&Bh[bkr][bc0])      = rbh[0];
        *reinterpret_cast<uint4*>(&Bh[bkr][bc0 + 8])  = rbh[1];
        *reinterpret_cast<uint4*>(&Bl[bkr][bc0])      = rbl[0];
        *reinterpret_cast<uint4*>(&Bl[bkr][bc0 + 8])  = rbl[1];
        __syncthreads();

        if (k0 + BKT < K) {
            size_t aoff = (size_t)(bm + arow) * K + (k0 + BKT) + ak0;
            size_t boff = (size_t)(k0 + BKT + bkr) * N + bn + bc0;
            ra[0] = inM ? *reinterpret_cast<const uint4*>(Ag + aoff) : zero4;
            ra[1] = inM ? *reinterpret_cast<const uint4*>(Ag + aoff + 8) : zero4;
            rbh[0] = *reinterpret_cast<const uint4*>(Bgh + boff);
            rbh[1] = *reinterpret_cast<const uint4*>(Bgh + boff + 8);
            rbl[0] = *reinterpret_cast<const uint4*>(Bgl + boff);
            rbl[1] = *reinterpret_cast<const uint4*>(Bgl + boff + 8);
        }

#pragma unroll
        for (int kk = 0; kk < BKT; kk += 16) {
            unsigned ahi[2][4];
            int lr = lane & 15;
            int acol = kk + ((lane >> 4) << 3);
#pragma unroll
            for (int mt = 0; mt < 2; mt++) {
                int r = warpM * 32 + mt * 16 + lr;
                ldsm_x4(ahi[mt], a_base + (unsigned)(r * ASTR + acol) * 2u);
            }
            int kr = kk + (lane & 15);
            int cgrp = (lane >> 4) << 3;
#pragma unroll
            for (int ntp = 0; ntp < 8; ntp += 2) {
                int n0 = warpN * 64 + ntp * 8;
                unsigned boff2 = (unsigned)(kr * BSTR + n0 + cgrp) * 2u;
                unsigned bh[4], bl[4];
                ldsm_x4t(bh, b_base_h + boff2);
                ldsm_x4t(bl, b_base_l + boff2);
#pragma unroll
                for (int mt = 0; mt < 2; mt++) {
                    mma_f16(acc[mt][ntp],     ahi[mt], bh[0], bh[1]);
                    mma_f16(acc[mt][ntp],     ahi[mt], bl[0], bl[1]);
                    mma_f16(acc[mt][ntp + 1], ahi[mt], bh[2], bh[3]);
                    mma_f16(acc[mt][ntp + 1], ahi[mt], bl[2], bl[3]);
                }
            }
        }
        __syncthreads();
    }

    // ---- epilogue: write C + fused column stats ----
    float cs[16], cq[16];
#pragma unroll
    for (int i = 0; i < 16; i++) { cs[i] = 0.f; cq[i] = 0.f; }

#pragma unroll
    for (int mt = 0; mt < 2; mt++) {
#pragma unroll
        for (int half = 0; half < 2; half++) {
            int row = bm + warpM * 32 + mt * 16 + (lane >> 2) + half * 8;
            if (row >= M) continue;
#pragma unroll
            for (int nt = 0; nt < 8; nt++) {
                int col = bn + warpN * 64 + nt * 8 + (lane & 3) * 2;
                float v0 = acc[mt][nt][half * 2 + 0];
                float v1 = acc[mt][nt][half * 2 + 1];
                if (bias) { v0 += bias[col]; v1 += bias[col + 1]; }
                *reinterpret_cast<float2*>(C + (long long)row * N + col) =
                    make_float2(v0, v1);
                if (statSum) {
                    cs[nt * 2]     += v0; cq[nt * 2]     += v0 * v0;
                    cs[nt * 2 + 1] += v1; cq[nt * 2 + 1] += v1 * v1;
                }
            }
        }
    }
    if (statSum) {
#pragma unroll
        for (int i = 0; i < 16; i++) {
#pragma unroll
            for (int s = 4; s < 32; s <<= 1) {
                cs[i] += __shfl_xor_sync(0xffffffffu, cs[i], s);
                cq[i] += __shfl_xor_sync(0xffffffffu, cq[i], s);
            }
        }
        if (lane < 4) {
#pragma unroll
            for (int nt = 0; nt < 8; nt++) {
                int col = bn + warpN * 64 + nt * 8 + lane * 2;
                atomicAdd(&statSum[col],     cs[nt * 2]);
                atomicAdd(&statSq[col],      cq[nt * 2]);
                atomicAdd(&statSum[col + 1], cs[nt * 2 + 1]);
                atomicAdd(&statSq[col + 1],  cq[nt * 2 + 1]);
            }
        }
    }
}

// -------- bn coefs --------
__global__ void bn_coef_kernel(const float* __restrict__ sum, const float* __restrict__ sumsq,
                               const float* __restrict__ g, const float* __restrict__ beta) {
    int f = threadIdx.x;
    float invN = 1.0f / (float)NN;
    float mu = sum[f] * invN;
    float var = fmaxf(sumsq[f] * invN - mu * mu, 0.0f);
    float s = g[f] * rsqrtf(var + EPS);
    g_bna[f] = s;
    g_bnc[f] = beta[f] - s * mu;
}

// -------- segmented max pool (sorted batch), bn2+lrelu fused, fp16 out ------
__global__ __launch_bounds__(128)
void pool_seg_kernel(const float* __restrict__ P2) {
    int g = blockIdx.x;
    int f = threadIdx.x * 4;
    int s = g_gstart[g], e = g_gend[g];
    float4 a = *reinterpret_cast<const float4*>(g_bna + f);
    float4 c = *reinterpret_cast<const float4*>(g_bnc + f);
    float m0 = -INFINITY, m1 = -INFINITY, m2 = -INFINITY, m3 = -INFINITY;
    for (int r = s; r < e; r++) {
        float4 v = *reinterpret_cast<const float4*>(P2 + (long long)r * HH + f);
        float z0 = fmaf(a.x, v.x, c.x);
        float z1 = fmaf(a.y, v.y, c.y);
        float z2 = fmaf(a.z, v.z, c.z);
        float z3 = fmaf(a.w, v.w, c.w);
        z0 = z0 > 0.f ? z0 : SLOPE * z0;
        z1 = z1 > 0.f ? z1 : SLOPE * z1;
        z2 = z2 > 0.f ? z2 : SLOPE * z2;
        z3 = z3 > 0.f ? z3 : SLOPE * z3;
        m0 = fmaxf(m0, z0); m1 = fmaxf(m1, z1);
        m2 = fmaxf(m2, z2); m3 = fmaxf(m3, z3);
    }
    float vv[4];
    if (e <= s) { vv[0] = vv[1] = vv[2] = vv[3] = 0.f; }
    else        { vv[0] = m0; vv[1] = m1; vv[2] = m2; vv[3] = m3; }
    round_store4(g_plh, (long long)g * HH + f, vv);
}

// -------- host launch --------
extern "C" void kernel_launch(void* const* d_in, const int* in_sizes, int n_in,
                              void* d_out, int out_size) {
    const float* x      = (const float*)d_in[0];
    const int*   ei     = (const int*)d_in[1];
    const int*   bt     = (const int*)d_in[2];
    const float* W1     = (const float*)d_in[3];
    const float* b1     = (const float*)d_in[4];
    const float* g1     = (const float*)d_in[5];
    const float* beta1  = (const float*)d_in[6];
    const float* W2     = (const float*)d_in[7];
    const float* b2     = (const float*)d_in[8];
    const float* g2     = (const float*)d_in[9];
    const float* beta2  = (const float*)d_in[10];
    const float* Wf     = (const float*)d_in[11];
    const float* bf     = (const float*)d_in[12];
    float* out = (float*)d_out;

    const int* erow = ei;
    const int* ecol = ei + EE;

    float *buf1, *buf3, *stats;
    __half *xah, *zah, *plh;
    __half *w1h, *w1l, *w2h, *w2l, *wfh, *wfl;
    cudaGetSymbolAddress((void**)&buf1, g_buf1);
    cudaGetSymbolAddress((void**)&buf3, g_buf3);
    cudaGetSymbolAddress((void**)&stats, g_stats);
    cudaGetSymbolAddress((void**)&xah, g_xah);
    cudaGetSymbolAddress((void**)&zah, g_zah);
    cudaGetSymbolAddress((void**)&plh, g_plh);
    cudaGetSymbolAddress((void**)&w1h, g_w1h);
    cudaGetSymbolAddress((void**)&w1l, g_w1l);
    cudaGetSymbolAddress((void**)&w2h, g_w2h);
    cudaGetSymbolAddress((void**)&w2l, g_w2l);
    cudaGetSymbolAddress((void**)&wfh, g_wfh);
    cudaGetSymbolAddress((void**)&wfl, g_wfl);

    const int T = 256;
    init_kernel<<<(NN + T - 1) / T, T>>>();
    count_deg_kernel<<<(EE + T - 1) / T, T>>>(ecol);
    wsplit_kernel<<<(DINF * HH + T - 1) / T, T>>>(W1, w1h, w1l, DINF * HH);
    wsplit_kernel<<<(HH * HH + T - 1) / T, T>>>(W2, w2h, w2l, HH * HH);
    wsplit_kernel<<<(HH * OUTC + T - 1) / T, T>>>(Wf, wfh, wfl, HH * OUTC);
    scan_kernel<<<1, 1024>>>();
    dinv_kernel<<<(NN + T - 1) / T, T>>>();
    edge_fill_kernel<<<(EE + T - 1) / T, T>>>(erow, ecol);
    seg_bounds_kernel<<<(NN + T - 1) / T, T>>>(bt);

    int blk_gx = (int)(((long long)NN * 32 + T - 1) / T);
    int blk_gz = (int)(((long long)NN * 128 + T - 1) / T);

    // ---- layer 1: gather X (fp16 out), GEMM (+stats1 fused) ----
    gather_x_kernel<<<blk_gx, T>>>(x);
    {
        dim3 grid(HH / BN, (NN + BM - 1) / BM);
        gemm_f16p<<<grid, 256>>>(xah, w1h, w1l, b1, buf1,
                                 stats + 0, stats + HH, NN, HH, DINF);
    }
    bn_coef_kernel<<<1, HH>>>(stats + 0, stats + HH, g1, beta1);

    // ---- layer 2: gather Z (fp16 out), GEMM (+stats2 fused) ----
    gather_z_kernel<<<blk_gz, T>>>(buf1);
    {
        dim3 grid(HH / BN, (NN + BM - 1) / BM);
        gemm_f16p<<<grid, 256>>>(zah, w2h, w2l, b2, buf3,
                                 stats + 2 * HH, stats + 3 * HH, NN, HH, HH);
    }
    bn_coef_kernel<<<1, HH>>>(stats + 2 * HH, stats + 3 * HH, g2, beta2);

    // ---- segmented pool (bn2+lrelu fused, fp16 out) + final GEMM ----
    pool_seg_kernel<<<GG, 128>>>(buf3);
    {
        dim3 grid(OUTC / BN, (GG + BM - 1) / BM);
        gemm_f16p<<<grid, 256>>>(plh, wfh, wfl, bf, out,
                                 nullptr, nullptr, GG, OUTC, HH);
    }
}